// round 12
// baseline (speedup 1.0000x reference)
#include <cuda_runtime.h>
#include <math.h>
#include <stdint.h>

#define QN 2048
#define NPTS 32768
#define DM 256
#define KNN 8
#define NH 8
#define HDIM 64
#define STATE 64
#define DINN 512
#define CONVN 640
#define NPROJN 1160
#define HIDN 1024
#define CSZ 64
#define NCH 32

// ---------------- scratch ----------------
__device__ float g_q[QN*DM];
__device__ float g_fbar[QN*DM];
__device__ float g_vbar[QN*DM];
__device__ float g_x[QN*DM];
__device__ float g_tmp[QN*DM];
__device__ int   g_idx[QN*KNN];
__device__ int   g_inv[2*QN];
__device__ float g_xs[2*QN*DM];
__device__ float g_proj[2*QN*NPROJN];
__device__ float g_xbc[2*QN*CONVN];
__device__ float g_dts[2*QN*NH];
__device__ float g_Las[2*QN*NH];
__device__ float g_Hc[2*NH*NCH*HDIM*STATE];
__device__ float g_Hin[2*NH*NCH*HDIM*STATE];
__device__ float g_y[2*QN*DINN];
__device__ float g_gated[2*QN*DINN];
__device__ float g_ssmout[2*QN*DM];
__device__ float g_ffnh[QN*HIDN];

__device__ __forceinline__ float sigmoidf_(float x){ return 1.f/(1.f+expf(-x)); }
__device__ __forceinline__ float warpSum(float v){
  #pragma unroll
  for (int o=16;o;o>>=1) v += __shfl_xor_sync(0xffffffffu, v, o);
  return v;
}
__device__ __forceinline__ void mma_tf32(float* d, uint32_t a0,uint32_t a1,uint32_t a2,uint32_t a3,
                                         uint32_t b0,uint32_t b1){
  asm volatile(
    "mma.sync.aligned.m16n8k8.row.col.f32.tf32.tf32.f32 "
    "{%0,%1,%2,%3}, {%4,%5,%6,%7}, {%8,%9}, {%0,%1,%2,%3};"
    : "+f"(d[0]),"+f"(d[1]),"+f"(d[2]),"+f"(d[3])
    : "r"(a0),"r"(a1),"r"(a2),"r"(a3),"r"(b0),"r"(b1));
}
__device__ __forceinline__ void cpa16(uint32_t s, const float* g, bool v){
  int sz = v?16:0;
  asm volatile("cp.async.cg.shared.global [%0], [%1], 16, %2;" :: "r"(s), "l"(g), "r"(sz));
}

// ---------------- KNN (+ fused inv computation) ----------------
#define TPTS 2048
__global__ void knn_kernel(const float* __restrict__ qpos, const float* __restrict__ spos,
                           const int* __restrict__ order){
  __shared__ float sp[TPTS*3];
  {
    int id=blockIdx.x*256+threadIdx.x;
    if (id<2*QN) g_inv[(id/QN)*QN + order[id]] = id%QN;
  }
  int warp = threadIdx.x>>5, lane = threadIdx.x&31;
  int q = blockIdx.x*8 + warp;
  float qx=qpos[q*3+0], qy=qpos[q*3+1], qz=qpos[q*3+2];
  float qq = qx*qx+qy*qy+qz*qz;
  float bd[8]; int bi[8];
  #pragma unroll
  for (int j=0;j<8;j++){ bd[j]=3.0e38f; bi[j]=0x7fffffff; }
  for (int tile=0;tile<NPTS/TPTS;tile++){
    __syncthreads();
    for (int i=threadIdx.x;i<TPTS*3;i+=256) sp[i]=spos[tile*TPTS*3+i];
    __syncthreads();
    for (int p=lane;p<TPTS;p+=32){
      float sx=sp[3*p], sy=sp[3*p+1], sz=sp[3*p+2];
      float ss = sx*sx+sy*sy+sz*sz;
      float dot = qx*sx+qy*sy+qz*sz;
      float d2 = qq + ss - 2.f*dot;
      if (d2 < bd[7]){
        bd[7]=d2; bi[7]=tile*TPTS+p;
        for (int j=7;j>0;j--){
          if (bd[j]<bd[j-1]){ float td=bd[j];bd[j]=bd[j-1];bd[j-1]=td;
                              int ti=bi[j];bi[j]=bi[j-1];bi[j-1]=ti; }
          else break;
        }
      }
    }
  }
  for (int off=16;off;off>>=1){
    float od[8]; int oi[8];
    #pragma unroll
    for (int j=0;j<8;j++){
      od[j]=__shfl_xor_sync(0xffffffffu,bd[j],off);
      oi[j]=__shfl_xor_sync(0xffffffffu,bi[j],off);
    }
    float nd[8]; int ni[8]; int a=0,c=0;
    for (int t=0;t<8;t++){
      bool mine;
      if (a>=8) mine=false;
      else if (c>=8) mine=true;
      else mine = (bd[a]<od[c]) || (bd[a]==od[c] && bi[a]<=oi[c]);
      if (mine){ nd[t]=bd[a];ni[t]=bi[a];a++; } else { nd[t]=od[c];ni[t]=oi[c];c++; }
    }
    for (int j=0;j<8;j++){ bd[j]=nd[j]; bi[j]=ni[j]; }
  }
  if (lane==0){
    #pragma unroll
    for (int j=0;j<8;j++) g_idx[q*8+j]=bi[j];
  }
}

// ---------------- tf32 GEMM, in-block split-K=2, 512 threads ----------------
// Fixed 64x32 block tile, 16x16 warp tiles; warps 0-7 do K[0,K/2), 8-15 do K[K/2,K).
// Requires M%64==0, N%32==0 within bounds, K%32==0.
template<int S>
__global__ void __launch_bounds__(512) tgemm_sk(
    const float* __restrict__ A, const float* __restrict__ B,
    const float* __restrict__ bias, const float* __restrict__ emul,
    float* __restrict__ Cmat, int M, int Nn, int Kk, int act){
  constexpr int ROWS = 96;            // 64 A rows + 32 B rows
  constexpr int SLOTS = ROWS*4;       // float4 slots per 16-K tile
  __shared__ float Sm[2][S][ROWS][20];
  int tid=threadIdx.x;
  int half=tid>>8, htid=tid&255;
  int warp=tid>>5, lane=tid&31;
  int warp8=warp&7;
  int wm=(warp8&3)*16, wn=(warp8>>2)*16;
  int g=lane>>2, tig=lane&3;
  int row0=blockIdx.y*64, col0=blockIdx.x*32;
  int Khalf=Kk>>1;
  int Koff=half*Khalf;

  float acc[2][4];
  #pragma unroll
  for (int ni=0;ni<2;ni++)
    #pragma unroll
    for (int r=0;r<4;r++) acc[ni][r]=0.f;

  const float* gp[2]; uint32_t so[2]; bool actv[2];
  #pragma unroll
  for (int i=0;i<2;i++){
    int idx=htid+i*256;
    actv[i]=(idx<SLOTS);
    int idc=actv[i]? idx:0;
    int r=idc>>2, c=(idc&3)<<2;
    if (r<64) gp[i]=A+(size_t)(row0+r)*Kk+Koff+c;
    else      gp[i]=B+(size_t)(col0+(r-64))*Kk+Koff+c;
    so[i]=(uint32_t)__cvta_generic_to_shared(&Sm[half][0][r][c]);
  }
  constexpr uint32_t STGB=ROWS*20*4;
  auto issue=[&](int stage, int k0){
    #pragma unroll
    for (int i=0;i<2;i++)
      if (actv[i]) cpa16(so[i]+stage*STGB, gp[i]+k0, true);
  };

  int KT2=Khalf>>4;
  #pragma unroll
  for (int s=0;s<S-1;s++){
    if (s<KT2) issue(s, s<<4);
    asm volatile("cp.async.commit_group;" ::: "memory");
  }

  int stage=0;
  for (int kt=0;kt<KT2;kt++){
    asm volatile("cp.async.wait_group %0;" :: "n"(S-2) : "memory");
    __syncthreads();
    int p=stage;
    uint32_t af0[4], bf0[2][2];
    {
      int m=wm+g;
      af0[0]=__float_as_uint(Sm[half][p][m  ][tig  ]);
      af0[1]=__float_as_uint(Sm[half][p][m+8][tig  ]);
      af0[2]=__float_as_uint(Sm[half][p][m  ][tig+4]);
      af0[3]=__float_as_uint(Sm[half][p][m+8][tig+4]);
      #pragma unroll
      for (int ni=0;ni<2;ni++){
        int n=64+wn+ni*8+g;
        bf0[ni][0]=__float_as_uint(Sm[half][p][n][tig  ]);
        bf0[ni][1]=__float_as_uint(Sm[half][p][n][tig+4]);
      }
    }
    int nt=kt+S-1;
    if (nt<KT2) issue(nt%S, nt<<4);
    asm volatile("cp.async.commit_group;" ::: "memory");
    uint32_t af1[4], bf1[2][2];
    {
      int m=wm+g;
      af1[0]=__float_as_uint(Sm[half][p][m  ][8+tig  ]);
      af1[1]=__float_as_uint(Sm[half][p][m+8][8+tig  ]);
      af1[2]=__float_as_uint(Sm[half][p][m  ][8+tig+4]);
      af1[3]=__float_as_uint(Sm[half][p][m+8][8+tig+4]);
      #pragma unroll
      for (int ni=0;ni<2;ni++){
        int n=64+wn+ni*8+g;
        bf1[ni][0]=__float_as_uint(Sm[half][p][n][8+tig  ]);
        bf1[ni][1]=__float_as_uint(Sm[half][p][n][8+tig+4]);
      }
    }
    #pragma unroll
    for (int ni=0;ni<2;ni++)
      mma_tf32(acc[ni], af0[0],af0[1],af0[2],af0[3], bf0[ni][0],bf0[ni][1]);
    #pragma unroll
    for (int ni=0;ni<2;ni++)
      mma_tf32(acc[ni], af1[0],af1[1],af1[2],af1[3], bf1[ni][0],bf1[ni][1]);
    stage = (stage+1==S)? 0 : stage+1;
  }

  // cross-half reduction through smem
  __syncthreads();
  float* red=&Sm[0][0][0][0];       // 2048 floats needed, plenty available
  if (half==1){
    int base=(warp8*32+lane)*8;
    #pragma unroll
    for (int ni=0;ni<2;ni++)
      #pragma unroll
      for (int r=0;r<4;r++) red[base+ni*4+r]=acc[ni][r];
  }
  __syncthreads();
  if (half==0){
    int base=(warp8*32+lane)*8;
    #pragma unroll
    for (int ni=0;ni<2;ni++)
      #pragma unroll
      for (int r=0;r<4;r++) acc[ni][r]+=red[base+ni*4+r];
    int rr0=row0+wm+g;
    #pragma unroll
    for (int ni=0;ni<2;ni++){
      int c=col0+wn+ni*8+2*tig;
      if (c+1<Nn){
        #pragma unroll
        for (int hh=0;hh<2;hh++){
          int rr=rr0+hh*8;
          float v0=acc[ni][hh*2+0], v1=acc[ni][hh*2+1];
          if (emul){ v0*=emul[(size_t)rr*Nn+c]; v1*=emul[(size_t)rr*Nn+c+1]; }
          if (bias){ v0+=bias[c]; v1+=bias[c+1]; }
          if (act==1){
            v0=0.5f*v0*(1.f+erff(v0*0.70710678118654752f));
            v1=0.5f*v1*(1.f+erff(v1*0.70710678118654752f));
          }
          *(float2*)&Cmat[(size_t)rr*Nn+c]=make_float2(v0,v1);
        }
      }
    }
  }
}

// ---------------- tf32 GEMM, cp.async S-stage + fragment double buffering (big tiles) ----------------
template<int TBM_, int TBN_, int WM, int WN, int NTHR, int S>
__global__ void __launch_bounds__(NTHR) tgemm_kernel(
    const float* __restrict__ A, const float* __restrict__ B,
    const float* __restrict__ bias, const float* __restrict__ emul,
    float* __restrict__ Cmat, int M, int Nn, int Kk, int act){
  constexpr int MW = TBM_/WM;
  constexpr int MI = WM/16, NI = WN/8;
  constexpr int ROWS = TBM_+TBN_;
  constexpr int SLOTS = ROWS*4;
  constexpr int CNT = (SLOTS+NTHR-1)/NTHR;
  __shared__ float Sm[S][ROWS][20];
  int tid=threadIdx.x, warp=tid>>5, lane=tid&31;
  int wm=(warp%MW)*WM, wn=(warp/MW)*WN;
  int g=lane>>2, tig=lane&3;
  int row0=blockIdx.y*TBM_, col0=blockIdx.x*TBN_;

  float acc[MI][NI][4];
  #pragma unroll
  for (int mi=0;mi<MI;mi++)
    #pragma unroll
    for (int ni=0;ni<NI;ni++)
      #pragma unroll
      for (int r=0;r<4;r++) acc[mi][ni][r]=0.f;

  const float* gp[CNT]; uint32_t so[CNT]; bool val[CNT]; bool actv[CNT];
  #pragma unroll
  for (int i=0;i<CNT;i++){
    int idx=tid+i*NTHR;
    actv[i]=(idx<SLOTS);
    int idc = actv[i]? idx : 0;
    int r=idc>>2, c=(idc&3)<<2;
    if (r<TBM_){ gp[i]=A+(size_t)(row0+r)*Kk+c; val[i]=true; }
    else { int rb=r-TBM_; gp[i]=B+(size_t)(col0+rb)*Kk+c; val[i]=(col0+rb)<Nn; }
    so[i]=(uint32_t)__cvta_generic_to_shared(&Sm[0][r][c]);
  }
  constexpr uint32_t STGB=ROWS*20*4;
  auto issue=[&](int stage, int k0){
    #pragma unroll
    for (int i=0;i<CNT;i++)
      if (actv[i]) cpa16(so[i]+stage*STGB, gp[i]+k0, val[i]);
  };

  int KT=Kk>>4;
  #pragma unroll
  for (int s=0;s<S-1;s++){
    if (s<KT) issue(s, s<<4);
    asm volatile("cp.async.commit_group;" ::: "memory");
  }

  int stage=0;
  for (int kt=0;kt<KT;kt++){
    asm volatile("cp.async.wait_group %0;" :: "n"(S-2) : "memory");
    __syncthreads();
    int p=stage;
    uint32_t af0[MI][4], bf0[NI][2];
    #pragma unroll
    for (int mi=0;mi<MI;mi++){
      int m=wm+mi*16+g;
      af0[mi][0]=__float_as_uint(Sm[p][m  ][tig  ]);
      af0[mi][1]=__float_as_uint(Sm[p][m+8][tig  ]);
      af0[mi][2]=__float_as_uint(Sm[p][m  ][tig+4]);
      af0[mi][3]=__float_as_uint(Sm[p][m+8][tig+4]);
    }
    #pragma unroll
    for (int ni=0;ni<NI;ni++){
      int n=TBM_+wn+ni*8+g;
      bf0[ni][0]=__float_as_uint(Sm[p][n][tig  ]);
      bf0[ni][1]=__float_as_uint(Sm[p][n][tig+4]);
    }
    int nt=kt+S-1;
    if (nt<KT) issue(nt%S, nt<<4);
    asm volatile("cp.async.commit_group;" ::: "memory");
    uint32_t af1[MI][4], bf1[NI][2];
    #pragma unroll
    for (int mi=0;mi<MI;mi++){
      int m=wm+mi*16+g;
      af1[mi][0]=__float_as_uint(Sm[p][m  ][8+tig  ]);
      af1[mi][1]=__float_as_uint(Sm[p][m+8][8+tig  ]);
      af1[mi][2]=__float_as_uint(Sm[p][m  ][8+tig+4]);
      af1[mi][3]=__float_as_uint(Sm[p][m+8][8+tig+4]);
    }
    #pragma unroll
    for (int ni=0;ni<NI;ni++){
      int n=TBM_+wn+ni*8+g;
      bf1[ni][0]=__float_as_uint(Sm[p][n][8+tig  ]);
      bf1[ni][1]=__float_as_uint(Sm[p][n][8+tig+4]);
    }
    #pragma unroll
    for (int mi=0;mi<MI;mi++)
      #pragma unroll
      for (int ni=0;ni<NI;ni++)
        mma_tf32(acc[mi][ni], af0[mi][0],af0[mi][1],af0[mi][2],af0[mi][3],
                 bf0[ni][0],bf0[ni][1]);
    #pragma unroll
    for (int mi=0;mi<MI;mi++)
      #pragma unroll
      for (int ni=0;ni<NI;ni++)
        mma_tf32(acc[mi][ni], af1[mi][0],af1[mi][1],af1[mi][2],af1[mi][3],
                 bf1[ni][0],bf1[ni][1]);
    stage = (stage+1==S)? 0 : stage+1;
  }
  #pragma unroll
  for (int mi=0;mi<MI;mi++){
    int r=row0+wm+mi*16+g;
    #pragma unroll
    for (int ni=0;ni<NI;ni++){
      int c=col0+wn+ni*8+2*tig;
      if (c+1<Nn){
        #pragma unroll
        for (int half=0;half<2;half++){
          int rr=r+half*8;
          float v0=acc[mi][ni][half*2+0], v1=acc[mi][ni][half*2+1];
          if (emul){ v0*=emul[(size_t)rr*Nn+c]; v1*=emul[(size_t)rr*Nn+c+1]; }
          if (bias){ v0+=bias[c]; v1+=bias[c+1]; }
          if (act==1){
            v0=0.5f*v0*(1.f+erff(v0*0.70710678118654752f));
            v1=0.5f*v1*(1.f+erff(v1*0.70710678118654752f));
          }
          *(float2*)&Cmat[(size_t)rr*Nn+c]=make_float2(v0,v1);
        }
      }
    }
  }
}

// ---------------- mixbar: warp per query ----------------
__global__ void mixbar2_kernel(const float* __restrict__ wk, const float* __restrict__ wb,
                               const float* __restrict__ feats){
  int warp=threadIdx.x>>5, lane=threadIdx.x&31;
  int q=blockIdx.x*8+warp;
  const float4* q4=(const float4*)g_q;
  float4 qa=q4[q*64+lane], qb=q4[q*64+32+lane];
  const float4* w4=(const float4*)wk;
  float logit[8];
  #pragma unroll
  for (int k=0;k<8;k++){
    float4 wa=w4[k*64+lane], wb4=w4[k*64+32+lane];
    float p=qa.x*wa.x+qa.y*wa.y+qa.z*wa.z+qa.w*wa.w
           +qb.x*wb4.x+qb.y*wb4.y+qb.z*wb4.z+qb.w*wb4.w;
    logit[k]=warpSum(p)+wb[k];
  }
  float m=logit[0];
  #pragma unroll
  for (int k=1;k<8;k++) m=fmaxf(m,logit[k]);
  float s=0.f; float kw[8];
  #pragma unroll
  for (int k=0;k<8;k++){ kw[k]=expf(logit[k]-m); s+=kw[k]; }
  float inv=1.f/s;
  const float4* f4=(const float4*)feats;
  float4 acc0=make_float4(0,0,0,0), acc1=make_float4(0,0,0,0);
  #pragma unroll
  for (int k=0;k<8;k++){
    float w=kw[k]*inv;
    int idx=g_idx[q*8+k];
    float4 fa=f4[(size_t)idx*64+lane], fb=f4[(size_t)idx*64+32+lane];
    acc0.x+=w*fa.x; acc0.y+=w*fa.y; acc0.z+=w*fa.z; acc0.w+=w*fa.w;
    acc1.x+=w*fb.x; acc1.y+=w*fb.y; acc1.z+=w*fb.z; acc1.w+=w*fb.w;
  }
  float4* o4=(float4*)g_fbar;
  o4[q*64+lane]=acc0; o4[q*64+32+lane]=acc1;
}

// ---------------- warp-per-row LayerNorm: out = LN(a + b) ----------------
__global__ void lnw_kernel(float* __restrict__ out, const float* __restrict__ a,
                           const float* __restrict__ b){
  int row=blockIdx.x*8 + (threadIdx.x>>5), lane=threadIdx.x&31;
  const float4* a4=(const float4*)a; const float4* b4=(const float4*)b;
  float4 v0=a4[row*64+lane], v1=a4[row*64+32+lane];
  float4 w0=b4[row*64+lane], w1=b4[row*64+32+lane];
  v0.x+=w0.x;v0.y+=w0.y;v0.z+=w0.z;v0.w+=w0.w;
  v1.x+=w1.x;v1.y+=w1.y;v1.z+=w1.z;v1.w+=w1.w;
  float s=warpSum(v0.x+v0.y+v0.z+v0.w+v1.x+v1.y+v1.z+v1.w);
  float mean=s*(1.f/DM);
  float d0x=v0.x-mean,d0y=v0.y-mean,d0z=v0.z-mean,d0w=v0.w-mean;
  float d1x=v1.x-mean,d1y=v1.y-mean,d1z=v1.z-mean,d1w=v1.w-mean;
  float vs=warpSum(d0x*d0x+d0y*d0y+d0z*d0z+d0w*d0w+d1x*d1x+d1y*d1y+d1z*d1z+d1w*d1w);
  float r=rsqrtf(vs*(1.f/DM)+1e-5f);
  float4* o4=(float4*)out;
  o4[row*64+lane]   =make_float4(d0x*r,d0y*r,d0z*r,d0w*r);
  o4[row*64+32+lane]=make_float4(d1x*r,d1y*r,d1z*r,d1w*r);
}

// ---------------- warp-per-row LN + serialize ----------------
__global__ void lnserw_kernel(const int* __restrict__ order){
  int row=blockIdx.x*8 + (threadIdx.x>>5), lane=threadIdx.x&31;
  int src=order[row];
  const float4* a4=(const float4*)g_x;
  float4 v0=a4[src*64+lane], v1=a4[src*64+32+lane];
  float s=warpSum(v0.x+v0.y+v0.z+v0.w+v1.x+v1.y+v1.z+v1.w);
  float mean=s*(1.f/DM);
  float d0x=v0.x-mean,d0y=v0.y-mean,d0z=v0.z-mean,d0w=v0.w-mean;
  float d1x=v1.x-mean,d1y=v1.y-mean,d1z=v1.z-mean,d1w=v1.w-mean;
  float vs=warpSum(d0x*d0x+d0y*d0y+d0z*d0z+d0w*d0w+d1x*d1x+d1y*d1y+d1z*d1z+d1w*d1w);
  float r=rsqrtf(vs*(1.f/DM)+1e-5f);
  float4* o4=(float4*)g_xs;
  o4[row*64+lane]   =make_float4(d0x*r,d0y*r,d0z*r,d0w*r);
  o4[row*64+32+lane]=make_float4(d1x*r,d1y*r,d1z*r,d1w*r);
}

// ---------------- conv + silu: thread = (b, c4, 8 timesteps) ----------------
__global__ void conv8_kernel(const float* __restrict__ wconv, const float* __restrict__ bconv){
  int id=blockIdx.x*blockDim.x+threadIdx.x;
  int c4=id%160; int t8=(id/160)%(QN/8); int b=id/(160*(QN/8));
  int t0=t8*8;
  const float4* bc4=(const float4*)bconv;
  float4 bias=bc4[c4];
  const float4* w4=(const float4*)wconv;
  float4 w0=w4[c4*4+0], w1=w4[c4*4+1], w2=w4[c4*4+2], w3=w4[c4*4+3];
  const float4* p4=(const float4*)g_proj;
  float4 xv[11];
  #pragma unroll
  for (int i=0;i<11;i++){
    int tt=t0-3+i;
    xv[i] = (tt>=0)? p4[(size_t)(b*QN+tt)*(NPROJN/4) + DINN/4 + c4]
                   : make_float4(0.f,0.f,0.f,0.f);
  }
  float4* ob=(float4*)g_xbc;
  #pragma unroll
  for (int u=0;u<8;u++){
    float4 acc=bias;
    #pragma unroll
    for (int j=0;j<4;j++){
      float4 x=xv[u+j];
      acc.x+=x.x*(&w0.x)[j]; acc.y+=x.y*(&w1.x)[j];
      acc.z+=x.z*(&w2.x)[j]; acc.w+=x.w*(&w3.x)[j];
    }
    acc.x*=sigmoidf_(acc.x); acc.y*=sigmoidf_(acc.y);
    acc.z*=sigmoidf_(acc.z); acc.w*=sigmoidf_(acc.w);
    ob[(size_t)(b*QN+t0+u)*160 + c4]=acc;
  }
}

// ---------------- chunkH with fused dt/La scan ----------------
__global__ void chunkH_kernel(const float* __restrict__ alog, const float* __restrict__ dtb){
  __shared__ float Xs[CSZ][HDIM], Bw[CSZ][STATE+1];
  __shared__ float La[CSZ], wv[CSZ];
  int bid=blockIdx.x;
  int c=bid%NCH, h=(bid/NCH)%NH, b=bid/(NCH*NH);
  int tid=threadIdx.x;
  int r0=b*QN + c*CSZ;
  float dtloc=0.f;
  if (tid<CSZ){
    int row=r0+tid;
    float raw = g_proj[(size_t)row*NPROJN + DINN+CONVN + h] + dtb[h];
    dtloc = raw>20.f? raw : log1pf(expf(raw));
    g_dts[row*NH+h]=dtloc;
    float A=-expf(alog[h]);
    La[tid]=dtloc*A;
  }
  __syncthreads();
  for (int o=1;o<CSZ;o<<=1){
    float v=0.f;
    if (tid<CSZ && tid>=o) v=La[tid-o];
    __syncthreads();
    if (tid<CSZ) La[tid]+=v;
    __syncthreads();
  }
  if (tid<CSZ) g_Las[(r0+tid)*NH+h]=La[tid];
  __syncthreads();
  if (tid<CSZ) wv[tid]=expf(La[CSZ-1]-La[tid])*dtloc;
  __syncthreads();
  for (int i=tid;i<CSZ*STATE;i+=256){
    int s=i>>6, k=i&63;
    const float* xr=&g_xbc[(size_t)(r0+s)*CONVN];
    Xs[s][k]=xr[h*HDIM+k];
    Bw[s][k]=xr[DINN+k]*wv[s];
  }
  __syncthreads();
  int hb=(tid>>4)<<2, sb=(tid&15)<<2;
  float acc[4][4];
  #pragma unroll
  for (int i=0;i<4;i++){ acc[i][0]=0;acc[i][1]=0;acc[i][2]=0;acc[i][3]=0; }
  for (int s=0;s<CSZ;s++){
    float xv[4], bv[4];
    #pragma unroll
    for (int i=0;i<4;i++) xv[i]=Xs[s][hb+i];
    #pragma unroll
    for (int j=0;j<4;j++) bv[j]=Bw[s][sb+j];
    #pragma unroll
    for (int i=0;i<4;i++)
      #pragma unroll
      for (int j=0;j<4;j++) acc[i][j]+=xv[i]*bv[j];
  }
  float* Hg=&g_Hc[(size_t)bid*HDIM*STATE];
  #pragma unroll
  for (int i=0;i<4;i++)
    #pragma unroll
    for (int j=0;j<4;j++)
      Hg[(hb+i)*STATE + sb+j]=acc[i][j];
}

// ---------------- carry: 128 blocks ----------------
__global__ void carry_kernel(){
  int bh=blockIdx.x>>3;
  int off=(blockIdx.x&7)*512 + threadIdx.x;
  int b=bh>>3, h=bh&7;
  size_t base0=(size_t)(bh*NCH)*HDIM*STATE;
  float hr=0.f;
  float nxt=g_Hc[base0+off];
  for (int c=0;c<NCH;c++){
    float Lend=g_Las[(b*QN + c*CSZ + CSZ-1)*NH + h];
    float f=expf(Lend);
    float cur=nxt;
    if (c+1<NCH) nxt=g_Hc[base0+(size_t)(c+1)*HDIM*STATE+off];
    g_Hin[base0+(size_t)c*HDIM*STATE+off]=hr;
    hr=f*hr+cur;
  }
}

// ---------------- fully fused P + y_intra + y_inter ----------------
__global__ void pyfull_kernel(const float* __restrict__ Dh){
  __shared__ float S1[CSZ][STATE+1];
  __shared__ float S2[CSZ][STATE+1];
  __shared__ float La[CSZ], dtv[CSZ];
  int bid=blockIdx.x;
  int c=bid%NCH, h=(bid/NCH)%NH, b=bid/(NCH*NH);
  int tid=threadIdx.x;
  int r0=b*QN + c*CSZ;
  if (tid<CSZ){ La[tid]=g_Las[(r0+tid)*NH+h]; dtv[tid]=g_dts[(r0+tid)*NH+h]; }
  for (int i=tid;i<CSZ*STATE;i+=256){
    int s=i>>6, st=i&63;
    const float* xr=&g_xbc[(size_t)(r0+s)*CONVN];
    S1[s][st]=xr[DINN+st];
    S2[s][st]=xr[DINN+STATE+st];
  }
  __syncthreads();
  int tb=(tid>>4)<<2, sb=(tid&15)<<2;
  float acc[4][4];
  #pragma unroll
  for (int i=0;i<4;i++){ acc[i][0]=0;acc[i][1]=0;acc[i][2]=0;acc[i][3]=0; }
  for (int k=0;k<STATE;k++){
    float cv[4], bv[4];
    #pragma unroll
    for (int i=0;i<4;i++) cv[i]=S2[tb+i][k];
    #pragma unroll
    for (int j=0;j<4;j++) bv[j]=S1[sb+j][k];
    #pragma unroll
    for (int i=0;i<4;i++)
      #pragma unroll
      for (int j=0;j<4;j++) acc[i][j]+=cv[i]*bv[j];
  }
  float Pv[4][4];
  #pragma unroll
  for (int i=0;i<4;i++){
    int t=tb+i;
    #pragma unroll
    for (int j=0;j<4;j++){
      int s=sb+j;
      Pv[i][j]=(s<=t)? expf(La[t]-La[s])*dtv[s]*acc[i][j] : 0.f;
    }
  }
  __syncthreads();
  const float* Hg=&g_Hin[(size_t)bid*HDIM*STATE];
  for (int i=tid;i<HDIM*STATE;i+=256) S1[i>>6][i&63]=Hg[i];
  __syncthreads();
  float y2[4][4];
  #pragma unroll
  for (int i=0;i<4;i++){ y2[i][0]=0;y2[i][1]=0;y2[i][2]=0;y2[i][3]=0; }
  for (int k=0;k<STATE;k++){
    float cv[4], hv[4];
    #pragma unroll
    for (int i=0;i<4;i++) cv[i]=S2[tb+i][k];
    #pragma unroll
    for (int j=0;j<4;j++) hv[j]=S1[sb+j][k];
    #pragma unroll
    for (int i=0;i<4;i++)
      #pragma unroll
      for (int j=0;j<4;j++) y2[i][j]+=cv[i]*hv[j];
  }
  __syncthreads();
  #pragma unroll
  for (int i=0;i<4;i++)
    #pragma unroll
    for (int j=0;j<4;j++) S2[tb+i][sb+j]=Pv[i][j];
  for (int i=tid;i<CSZ*HDIM;i+=256){
    int s=i>>6,k=i&63;
    S1[s][k]=g_xbc[(size_t)(r0+s)*CONVN + h*HDIM + k];
  }
  __syncthreads();
  int hb=sb;
  float y1[4][4];
  #pragma unroll
  for (int i=0;i<4;i++){ y1[i][0]=0;y1[i][1]=0;y1[i][2]=0;y1[i][3]=0; }
  for (int s=0;s<CSZ;s++){
    float pv[4], xv[4];
    #pragma unroll
    for (int i=0;i<4;i++) pv[i]=S2[tb+i][s];
    #pragma unroll
    for (int j=0;j<4;j++) xv[j]=S1[s][hb+j];
    #pragma unroll
    for (int i=0;i<4;i++)
      #pragma unroll
      for (int j=0;j<4;j++) y1[i][j]+=pv[i]*xv[j];
  }
  float dh=Dh[h];
  #pragma unroll
  for (int i=0;i<4;i++){
    int t=tb+i;
    float f=expf(La[t]);
    #pragma unroll
    for (int j=0;j<4;j++)
      g_y[(size_t)(r0+t)*DINN + h*HDIM + hb+j] = y1[i][j] + dh*S1[t][hb+j] + f*y2[i][j];
  }
}

// ---------------- warp-per-row gated RMSNorm over 512 ----------------
__global__ void gate_rmsw_kernel(const float* __restrict__ rmsw){
  int row=blockIdx.x*8 + (threadIdx.x>>5), lane=threadIdx.x&31;
  const float4* y4=(const float4*)g_y;
  const float4* p4=(const float4*)g_proj;
  const float4* w4=(const float4*)rmsw;
  float4 gg[4];
  float ssum=0.f;
  #pragma unroll
  for (int i=0;i<4;i++){
    float4 y=y4[(size_t)row*128 + i*32 + lane];
    float4 z=p4[(size_t)row*(NPROJN/4) + i*32 + lane];
    gg[i].x=y.x*(z.x*sigmoidf_(z.x));
    gg[i].y=y.y*(z.y*sigmoidf_(z.y));
    gg[i].z=y.z*(z.z*sigmoidf_(z.z));
    gg[i].w=y.w*(z.w*sigmoidf_(z.w));
    ssum+=gg[i].x*gg[i].x+gg[i].y*gg[i].y+gg[i].z*gg[i].z+gg[i].w*gg[i].w;
  }
  ssum=warpSum(ssum);
  float r=rsqrtf(ssum*(1.f/DINN)+1e-5f);
  float4* o4=(float4*)g_gated;
  #pragma unroll
  for (int i=0;i<4;i++){
    float4 w=w4[i*32+lane];
    o4[(size_t)row*128 + i*32 + lane]=make_float4(gg[i].x*r*w.x, gg[i].y*r*w.y,
                                                  gg[i].z*r*w.z, gg[i].w*r*w.w);
  }
}

// ---------------- warp-per-row unsort + average + residual + LN ----------------
__global__ void merge_lnw_kernel(){
  int q=blockIdx.x*8 + (threadIdx.x>>5), lane=threadIdx.x&31;
  int i0=g_inv[q], i1=g_inv[QN+q];
  const float4* x4=(const float4*)g_x;
  const float4* s4=(const float4*)g_ssmout;
  float4 v0=x4[q*64+lane], v1=x4[q*64+32+lane];
  float4 a0=s4[(size_t)i0*64+lane], a1=s4[(size_t)i0*64+32+lane];
  float4 b0=s4[(size_t)(QN+i1)*64+lane], b1=s4[(size_t)(QN+i1)*64+32+lane];
  v0.x+=0.5f*(a0.x+b0.x); v0.y+=0.5f*(a0.y+b0.y);
  v0.z+=0.5f*(a0.z+b0.z); v0.w+=0.5f*(a0.w+b0.w);
  v1.x+=0.5f*(a1.x+b1.x); v1.y+=0.5f*(a1.y+b1.y);
  v1.z+=0.5f*(a1.z+b1.z); v1.w+=0.5f*(a1.w+b1.w);
  float s=warpSum(v0.x+v0.y+v0.z+v0.w+v1.x+v1.y+v1.z+v1.w);
  float mean=s*(1.f/DM);
  float d0x=v0.x-mean,d0y=v0.y-mean,d0z=v0.z-mean,d0w=v0.w-mean;
  float d1x=v1.x-mean,d1y=v1.y-mean,d1z=v1.z-mean,d1w=v1.w-mean;
  float vs=warpSum(d0x*d0x+d0y*d0y+d0z*d0z+d0w*d0w+d1x*d1x+d1y*d1y+d1z*d1z+d1w*d1w);
  float r=rsqrtf(vs*(1.f/DM)+1e-5f);
  float4* o4=(float4*)g_x;
  o4[q*64+lane]   =make_float4(d0x*r,d0y*r,d0z*r,d0w*r);
  o4[q*64+32+lane]=make_float4(d1x*r,d1y*r,d1z*r,d1w*r);
}

// =====================================================================
extern "C" void kernel_launch(void* const* d_in, const int* in_sizes, int n_in,
                              void* d_out, int out_size){
  const float* query      = (const float*)d_in[0];
  const float* query_pos  = (const float*)d_in[1];
  const float* inst_feats = (const float*)d_in[2];
  const float* sp_coords  = (const float*)d_in[3];
  const float* w_q  = (const float*)d_in[4];
  const float* w_v  = (const float*)d_in[5];
  const float* w_o  = (const float*)d_in[6];
  const float* w_k  = (const float*)d_in[7];
  const float* w_b  = (const float*)d_in[8];
  const float* Win  = (const float*)d_in[9];
  const float* Wconv= (const float*)d_in[10];
  const float* bconv= (const float*)d_in[11];
  const float* Alog = (const float*)d_in[12];
  const float* Dh   = (const float*)d_in[13];
  const float* dtb  = (const float*)d_in[14];
  const float* rmsw = (const float*)d_in[15];
  const float* Wout = (const float*)d_in[16];
  const float* fw1  = (const float*)d_in[17];
  const float* fb1  = (const float*)d_in[18];
  const float* fw2  = (const float*)d_in[19];
  const float* fb2  = (const float*)d_in[20];
  const int*   order= (const int*)  d_in[21];
  float* out = (float*)d_out;

  float *pq,*pfbar,*pvbar,*ptmp,*px,*pxs,*pproj,*pgated,*pssm,*pffnh;
  cudaGetSymbolAddress((void**)&pq,    g_q);
  cudaGetSymbolAddress((void**)&pfbar, g_fbar);
  cudaGetSymbolAddress((void**)&pvbar, g_vbar);
  cudaGetSymbolAddress((void**)&ptmp,  g_tmp);
  cudaGetSymbolAddress((void**)&px,    g_x);
  cudaGetSymbolAddress((void**)&pxs,   g_xs);
  cudaGetSymbolAddress((void**)&pproj, g_proj);
  cudaGetSymbolAddress((void**)&pgated,g_gated);
  cudaGetSymbolAddress((void**)&pssm,  g_ssmout);
  cudaGetSymbolAddress((void**)&pffnh, g_ffnh);

  auto gridS=[](int m,int n){ return dim3((unsigned)(n/32),(unsigned)(m/64)); };
  auto gridB=[](int m,int n){ return dim3((unsigned)((n+63)/64),(unsigned)(m/128)); };

  // --- stage 1 (launch #4 = wv split-K GEMM for the profiler) ---
  knn_kernel<<<QN/8,256>>>(query_pos, sp_coords, order);
  tgemm_sk<3><<<gridS(QN,DM),512>>>(query, w_q, nullptr, nullptr, pq, QN, DM, DM, 0);
  mixbar2_kernel<<<QN/8,256>>>(w_k, w_b, inst_feats);
  tgemm_sk<3><<<gridS(QN,DM),512>>>(pfbar, w_v, nullptr, pq, pvbar, QN, DM, DM, 0);
  tgemm_sk<3><<<gridS(QN,DM),512>>>(pvbar, w_o, nullptr, nullptr, ptmp, QN, DM, DM, 0);
  lnw_kernel<<<QN/8,256>>>(px, ptmp, query);

  // --- stage 2: two Mamba2 layers ---
  for (int l=0;l<2;l++){
    lnserw_kernel<<<2*QN/8,256>>>(order);
    tgemm_kernel<128,64,32,32,256,3><<<gridB(2*QN,NPROJN),256>>>(pxs,
        Win + (size_t)l*NPROJN*DM, nullptr, nullptr, pproj, 2*QN, NPROJN, DM, 0);
    conv8_kernel<<<(2*(QN/8)*160)/256,256>>>(Wconv + (size_t)l*CONVN*4, bconv + (size_t)l*CONVN);
    chunkH_kernel<<<2*NH*NCH,256>>>(Alog + l*NH, dtb + l*NH);
    carry_kernel<<<2*NH*8,512>>>();
    pyfull_kernel<<<2*NH*NCH,256>>>(Dh + l*NH);
    gate_rmsw_kernel<<<2*QN/8,256>>>(rmsw + (size_t)l*DINN);
    tgemm_sk<3><<<gridS(2*QN,DM),512>>>(pgated,
        Wout + (size_t)l*DM*DINN, nullptr, nullptr, pssm, 2*QN, DM, DINN, 0);
    merge_lnw_kernel<<<QN/8,256>>>();
  }

  // --- stage 3: FFN + final LN ---
  tgemm_kernel<128,64,32,32,256,3><<<gridB(QN,HIDN),256>>>(px, fw1, fb1, nullptr, pffnh, QN, HIDN, DM, 1);
  tgemm_sk<3><<<gridS(QN,DM),512>>>(pffnh, fw2, fb2, nullptr, ptmp, QN, DM, HIDN, 0);
  lnw_kernel<<<QN/8,256>>>(out, ptmp, px);
}

// round 13
// speedup vs baseline: 1.0363x; 1.0363x over previous
#include <cuda_runtime.h>
#include <math.h>
#include <stdint.h>

#define QN 2048
#define NPTS 32768
#define DM 256
#define KNN 8
#define NH 8
#define HDIM 64
#define STATE 64
#define DINN 512
#define CONVN 640
#define NPROJN 1160
#define HIDN 1024
#define CSZ 64
#define NCH 32

// ---------------- scratch ----------------
__device__ float g_q[QN*DM];
__device__ float g_fbar[QN*DM];
__device__ float g_vbar[QN*DM];
__device__ float g_x[QN*DM];
__device__ float g_tmp[QN*DM];
__device__ int   g_idx[QN*KNN];
__device__ int   g_inv[2*QN];
__device__ float g_xs[2*QN*DM];
__device__ float g_proj[2*QN*NPROJN];
__device__ float g_xbc[2*QN*CONVN];
__device__ float g_dts[2*QN*NH];
__device__ float g_Las[2*QN*NH];
__device__ float g_Hc[2*NH*NCH*HDIM*STATE];
__device__ float g_Hin[2*NH*NCH*HDIM*STATE];
__device__ float g_y[2*QN*DINN];
__device__ float g_gated[2*QN*DINN];
__device__ float g_ssmout[2*QN*DM];
__device__ float g_ffnh[QN*HIDN];

__device__ __forceinline__ float sigmoidf_(float x){ return 1.f/(1.f+expf(-x)); }
__device__ __forceinline__ float warpSum(float v){
  #pragma unroll
  for (int o=16;o;o>>=1) v += __shfl_xor_sync(0xffffffffu, v, o);
  return v;
}
__device__ __forceinline__ void mma_tf32(float* d, uint32_t a0,uint32_t a1,uint32_t a2,uint32_t a3,
                                         uint32_t b0,uint32_t b1){
  asm volatile(
    "mma.sync.aligned.m16n8k8.row.col.f32.tf32.tf32.f32 "
    "{%0,%1,%2,%3}, {%4,%5,%6,%7}, {%8,%9}, {%0,%1,%2,%3};"
    : "+f"(d[0]),"+f"(d[1]),"+f"(d[2]),"+f"(d[3])
    : "r"(a0),"r"(a1),"r"(a2),"r"(a3),"r"(b0),"r"(b1));
}
__device__ __forceinline__ void cpa16(uint32_t s, const float* g, bool v){
  int sz = v?16:0;
  asm volatile("cp.async.cg.shared.global [%0], [%1], 16, %2;" :: "r"(s), "l"(g), "r"(sz));
}

// ---------------- KNN (+ fused inv computation), float4 tiles with precomputed norms ----------------
#define TPTS 2048
__global__ void knn_kernel(const float* __restrict__ qpos, const float* __restrict__ spos,
                           const int* __restrict__ order){
  __shared__ float4 sp[TPTS];
  {
    int id=blockIdx.x*256+threadIdx.x;
    if (id<2*QN) g_inv[(id/QN)*QN + order[id]] = id%QN;
  }
  int warp = threadIdx.x>>5, lane = threadIdx.x&31;
  int q = blockIdx.x*8 + warp;
  float qx=qpos[q*3+0], qy=qpos[q*3+1], qz=qpos[q*3+2];
  float qq = qx*qx+qy*qy+qz*qz;
  float bd[8]; int bi[8];
  #pragma unroll
  for (int j=0;j<8;j++){ bd[j]=3.0e38f; bi[j]=0x7fffffff; }
  for (int tile=0;tile<NPTS/TPTS;tile++){
    __syncthreads();
    for (int i=threadIdx.x;i<TPTS;i+=256){
      const float* p=&spos[(size_t)(tile*TPTS+i)*3];
      float sx=p[0], sy=p[1], sz=p[2];
      float ss=sx*sx+sy*sy+sz*sz;   // same op order as before
      sp[i]=make_float4(sx,sy,sz,ss);
    }
    __syncthreads();
    for (int p=lane;p<TPTS;p+=32){
      float4 s4=sp[p];
      float dot = qx*s4.x+qy*s4.y+qz*s4.z;
      float d2 = qq + s4.w - 2.f*dot;
      if (d2 < bd[7]){
        bd[7]=d2; bi[7]=tile*TPTS+p;
        for (int j=7;j>0;j--){
          if (bd[j]<bd[j-1]){ float td=bd[j];bd[j]=bd[j-1];bd[j-1]=td;
                              int ti=bi[j];bi[j]=bi[j-1];bi[j-1]=ti; }
          else break;
        }
      }
    }
  }
  for (int off=16;off;off>>=1){
    float od[8]; int oi[8];
    #pragma unroll
    for (int j=0;j<8;j++){
      od[j]=__shfl_xor_sync(0xffffffffu,bd[j],off);
      oi[j]=__shfl_xor_sync(0xffffffffu,bi[j],off);
    }
    float nd[8]; int ni[8]; int a=0,c=0;
    for (int t=0;t<8;t++){
      bool mine;
      if (a>=8) mine=false;
      else if (c>=8) mine=true;
      else mine = (bd[a]<od[c]) || (bd[a]==od[c] && bi[a]<=oi[c]);
      if (mine){ nd[t]=bd[a];ni[t]=bi[a];a++; } else { nd[t]=od[c];ni[t]=oi[c];c++; }
    }
    for (int j=0;j<8;j++){ bd[j]=nd[j]; bi[j]=ni[j]; }
  }
  if (lane==0){
    #pragma unroll
    for (int j=0;j<8;j++) g_idx[q*8+j]=bi[j];
  }
}

// ---------------- tf32 GEMM, cp.async S-stage + fragment double buffering ----------------
template<int TBM_, int TBN_, int WM, int WN, int NTHR, int S>
__global__ void __launch_bounds__(NTHR) tgemm_kernel(
    const float* __restrict__ A, const float* __restrict__ B,
    const float* __restrict__ bias, const float* __restrict__ emul,
    float* __restrict__ Cmat, int M, int Nn, int Kk, int act){
  constexpr int MW = TBM_/WM;
  constexpr int MI = WM/16, NI = WN/8;
  constexpr int ROWS = TBM_+TBN_;
  constexpr int SLOTS = ROWS*4;
  constexpr int CNT = (SLOTS+NTHR-1)/NTHR;
  __shared__ float Sm[S][ROWS][20];
  int tid=threadIdx.x, warp=tid>>5, lane=tid&31;
  int wm=(warp%MW)*WM, wn=(warp/MW)*WN;
  int g=lane>>2, tig=lane&3;
  int row0=blockIdx.y*TBM_, col0=blockIdx.x*TBN_;

  float acc[MI][NI][4];
  #pragma unroll
  for (int mi=0;mi<MI;mi++)
    #pragma unroll
    for (int ni=0;ni<NI;ni++)
      #pragma unroll
      for (int r=0;r<4;r++) acc[mi][ni][r]=0.f;

  const float* gp[CNT]; uint32_t so[CNT]; bool val[CNT]; bool actv[CNT];
  #pragma unroll
  for (int i=0;i<CNT;i++){
    int idx=tid+i*NTHR;
    actv[i]=(idx<SLOTS);
    int idc = actv[i]? idx : 0;
    int r=idc>>2, c=(idc&3)<<2;
    if (r<TBM_){ gp[i]=A+(size_t)(row0+r)*Kk+c; val[i]=true; }
    else { int rb=r-TBM_; gp[i]=B+(size_t)(col0+rb)*Kk+c; val[i]=(col0+rb)<Nn; }
    so[i]=(uint32_t)__cvta_generic_to_shared(&Sm[0][r][c]);
  }
  constexpr uint32_t STGB=ROWS*20*4;
  auto issue=[&](int stage, int k0){
    #pragma unroll
    for (int i=0;i<CNT;i++)
      if (actv[i]) cpa16(so[i]+stage*STGB, gp[i]+k0, val[i]);
  };

  int KT=Kk>>4;
  #pragma unroll
  for (int s=0;s<S-1;s++){
    if (s<KT) issue(s, s<<4);
    asm volatile("cp.async.commit_group;" ::: "memory");
  }

  int stage=0;
  for (int kt=0;kt<KT;kt++){
    asm volatile("cp.async.wait_group %0;" :: "n"(S-2) : "memory");
    __syncthreads();
    int p=stage;
    uint32_t af0[MI][4], bf0[NI][2];
    #pragma unroll
    for (int mi=0;mi<MI;mi++){
      int m=wm+mi*16+g;
      af0[mi][0]=__float_as_uint(Sm[p][m  ][tig  ]);
      af0[mi][1]=__float_as_uint(Sm[p][m+8][tig  ]);
      af0[mi][2]=__float_as_uint(Sm[p][m  ][tig+4]);
      af0[mi][3]=__float_as_uint(Sm[p][m+8][tig+4]);
    }
    #pragma unroll
    for (int ni=0;ni<NI;ni++){
      int n=TBM_+wn+ni*8+g;
      bf0[ni][0]=__float_as_uint(Sm[p][n][tig  ]);
      bf0[ni][1]=__float_as_uint(Sm[p][n][tig+4]);
    }
    int nt=kt+S-1;
    if (nt<KT) issue(nt%S, nt<<4);
    asm volatile("cp.async.commit_group;" ::: "memory");
    uint32_t af1[MI][4], bf1[NI][2];
    #pragma unroll
    for (int mi=0;mi<MI;mi++){
      int m=wm+mi*16+g;
      af1[mi][0]=__float_as_uint(Sm[p][m  ][8+tig  ]);
      af1[mi][1]=__float_as_uint(Sm[p][m+8][8+tig  ]);
      af1[mi][2]=__float_as_uint(Sm[p][m  ][8+tig+4]);
      af1[mi][3]=__float_as_uint(Sm[p][m+8][8+tig+4]);
    }
    #pragma unroll
    for (int ni=0;ni<NI;ni++){
      int n=TBM_+wn+ni*8+g;
      bf1[ni][0]=__float_as_uint(Sm[p][n][8+tig  ]);
      bf1[ni][1]=__float_as_uint(Sm[p][n][8+tig+4]);
    }
    #pragma unroll
    for (int mi=0;mi<MI;mi++)
      #pragma unroll
      for (int ni=0;ni<NI;ni++)
        mma_tf32(acc[mi][ni], af0[mi][0],af0[mi][1],af0[mi][2],af0[mi][3],
                 bf0[ni][0],bf0[ni][1]);
    #pragma unroll
    for (int mi=0;mi<MI;mi++)
      #pragma unroll
      for (int ni=0;ni<NI;ni++)
        mma_tf32(acc[mi][ni], af1[mi][0],af1[mi][1],af1[mi][2],af1[mi][3],
                 bf1[ni][0],bf1[ni][1]);
    stage = (stage+1==S)? 0 : stage+1;
  }
  #pragma unroll
  for (int mi=0;mi<MI;mi++){
    int r=row0+wm+mi*16+g;
    #pragma unroll
    for (int ni=0;ni<NI;ni++){
      int c=col0+wn+ni*8+2*tig;
      if (c+1<Nn){
        #pragma unroll
        for (int half=0;half<2;half++){
          int rr=r+half*8;
          float v0=acc[mi][ni][half*2+0], v1=acc[mi][ni][half*2+1];
          if (emul){ v0*=emul[(size_t)rr*Nn+c]; v1*=emul[(size_t)rr*Nn+c+1]; }
          if (bias){ v0+=bias[c]; v1+=bias[c+1]; }
          if (act==1){
            v0=0.5f*v0*(1.f+erff(v0*0.70710678118654752f));
            v1=0.5f*v1*(1.f+erff(v1*0.70710678118654752f));
          }
          *(float2*)&Cmat[(size_t)rr*Nn+c]=make_float2(v0,v1);
        }
      }
    }
  }
}

// ---------------- mixbar: warp per query ----------------
__global__ void mixbar2_kernel(const float* __restrict__ wk, const float* __restrict__ wb,
                               const float* __restrict__ feats){
  int warp=threadIdx.x>>5, lane=threadIdx.x&31;
  int q=blockIdx.x*8+warp;
  const float4* q4=(const float4*)g_q;
  float4 qa=q4[q*64+lane], qb=q4[q*64+32+lane];
  const float4* w4=(const float4*)wk;
  float logit[8];
  #pragma unroll
  for (int k=0;k<8;k++){
    float4 wa=w4[k*64+lane], wb4=w4[k*64+32+lane];
    float p=qa.x*wa.x+qa.y*wa.y+qa.z*wa.z+qa.w*wa.w
           +qb.x*wb4.x+qb.y*wb4.y+qb.z*wb4.z+qb.w*wb4.w;
    logit[k]=warpSum(p)+wb[k];
  }
  float m=logit[0];
  #pragma unroll
  for (int k=1;k<8;k++) m=fmaxf(m,logit[k]);
  float s=0.f; float kw[8];
  #pragma unroll
  for (int k=0;k<8;k++){ kw[k]=expf(logit[k]-m); s+=kw[k]; }
  float inv=1.f/s;
  const float4* f4=(const float4*)feats;
  float4 acc0=make_float4(0,0,0,0), acc1=make_float4(0,0,0,0);
  #pragma unroll
  for (int k=0;k<8;k++){
    float w=kw[k]*inv;
    int idx=g_idx[q*8+k];
    float4 fa=f4[(size_t)idx*64+lane], fb=f4[(size_t)idx*64+32+lane];
    acc0.x+=w*fa.x; acc0.y+=w*fa.y; acc0.z+=w*fa.z; acc0.w+=w*fa.w;
    acc1.x+=w*fb.x; acc1.y+=w*fb.y; acc1.z+=w*fb.z; acc1.w+=w*fb.w;
  }
  float4* o4=(float4*)g_fbar;
  o4[q*64+lane]=acc0; o4[q*64+32+lane]=acc1;
}

// ---------------- warp-per-row LayerNorm: out = LN(a + b) ----------------
__global__ void lnw_kernel(float* __restrict__ out, const float* __restrict__ a,
                           const float* __restrict__ b){
  int row=blockIdx.x*8 + (threadIdx.x>>5), lane=threadIdx.x&31;
  const float4* a4=(const float4*)a; const float4* b4=(const float4*)b;
  float4 v0=a4[row*64+lane], v1=a4[row*64+32+lane];
  float4 w0=b4[row*64+lane], w1=b4[row*64+32+lane];
  v0.x+=w0.x;v0.y+=w0.y;v0.z+=w0.z;v0.w+=w0.w;
  v1.x+=w1.x;v1.y+=w1.y;v1.z+=w1.z;v1.w+=w1.w;
  float s=warpSum(v0.x+v0.y+v0.z+v0.w+v1.x+v1.y+v1.z+v1.w);
  float mean=s*(1.f/DM);
  float d0x=v0.x-mean,d0y=v0.y-mean,d0z=v0.z-mean,d0w=v0.w-mean;
  float d1x=v1.x-mean,d1y=v1.y-mean,d1z=v1.z-mean,d1w=v1.w-mean;
  float vs=warpSum(d0x*d0x+d0y*d0y+d0z*d0z+d0w*d0w+d1x*d1x+d1y*d1y+d1z*d1z+d1w*d1w);
  float r=rsqrtf(vs*(1.f/DM)+1e-5f);
  float4* o4=(float4*)out;
  o4[row*64+lane]   =make_float4(d0x*r,d0y*r,d0z*r,d0w*r);
  o4[row*64+32+lane]=make_float4(d1x*r,d1y*r,d1z*r,d1w*r);
}

// ---------------- warp-per-row LN + serialize ----------------
__global__ void lnserw_kernel(const int* __restrict__ order){
  int row=blockIdx.x*8 + (threadIdx.x>>5), lane=threadIdx.x&31;
  int src=order[row];
  const float4* a4=(const float4*)g_x;
  float4 v0=a4[src*64+lane], v1=a4[src*64+32+lane];
  float s=warpSum(v0.x+v0.y+v0.z+v0.w+v1.x+v1.y+v1.z+v1.w);
  float mean=s*(1.f/DM);
  float d0x=v0.x-mean,d0y=v0.y-mean,d0z=v0.z-mean,d0w=v0.w-mean;
  float d1x=v1.x-mean,d1y=v1.y-mean,d1z=v1.z-mean,d1w=v1.w-mean;
  float vs=warpSum(d0x*d0x+d0y*d0y+d0z*d0z+d0w*d0w+d1x*d1x+d1y*d1y+d1z*d1z+d1w*d1w);
  float r=rsqrtf(vs*(1.f/DM)+1e-5f);
  float4* o4=(float4*)g_xs;
  o4[row*64+lane]   =make_float4(d0x*r,d0y*r,d0z*r,d0w*r);
  o4[row*64+32+lane]=make_float4(d1x*r,d1y*r,d1z*r,d1w*r);
}

// ---------------- conv + silu: thread = (b, c4, 8 timesteps) ----------------
__global__ void conv8_kernel(const float* __restrict__ wconv, const float* __restrict__ bconv){
  int id=blockIdx.x*blockDim.x+threadIdx.x;
  int c4=id%160; int t8=(id/160)%(QN/8); int b=id/(160*(QN/8));
  int t0=t8*8;
  const float4* bc4=(const float4*)bconv;
  float4 bias=bc4[c4];
  const float4* w4=(const float4*)wconv;
  float4 w0=w4[c4*4+0], w1=w4[c4*4+1], w2=w4[c4*4+2], w3=w4[c4*4+3];
  const float4* p4=(const float4*)g_proj;
  float4 xv[11];
  #pragma unroll
  for (int i=0;i<11;i++){
    int tt=t0-3+i;
    xv[i] = (tt>=0)? p4[(size_t)(b*QN+tt)*(NPROJN/4) + DINN/4 + c4]
                   : make_float4(0.f,0.f,0.f,0.f);
  }
  float4* ob=(float4*)g_xbc;
  #pragma unroll
  for (int u=0;u<8;u++){
    float4 acc=bias;
    #pragma unroll
    for (int j=0;j<4;j++){
      float4 x=xv[u+j];
      acc.x+=x.x*(&w0.x)[j]; acc.y+=x.y*(&w1.x)[j];
      acc.z+=x.z*(&w2.x)[j]; acc.w+=x.w*(&w3.x)[j];
    }
    acc.x*=sigmoidf_(acc.x); acc.y*=sigmoidf_(acc.y);
    acc.z*=sigmoidf_(acc.z); acc.w*=sigmoidf_(acc.w);
    ob[(size_t)(b*QN+t0+u)*160 + c4]=acc;
  }
}

// ---------------- chunkH with fused dt/La scan ----------------
__global__ void chunkH_kernel(const float* __restrict__ alog, const float* __restrict__ dtb){
  __shared__ float Xs[CSZ][HDIM], Bw[CSZ][STATE+1];
  __shared__ float La[CSZ], wv[CSZ];
  int bid=blockIdx.x;
  int c=bid%NCH, h=(bid/NCH)%NH, b=bid/(NCH*NH);
  int tid=threadIdx.x;
  int r0=b*QN + c*CSZ;
  float dtloc=0.f;
  if (tid<CSZ){
    int row=r0+tid;
    float raw = g_proj[(size_t)row*NPROJN + DINN+CONVN + h] + dtb[h];
    dtloc = raw>20.f? raw : log1pf(expf(raw));
    g_dts[row*NH+h]=dtloc;
    float A=-expf(alog[h]);
    La[tid]=dtloc*A;
  }
  __syncthreads();
  for (int o=1;o<CSZ;o<<=1){
    float v=0.f;
    if (tid<CSZ && tid>=o) v=La[tid-o];
    __syncthreads();
    if (tid<CSZ) La[tid]+=v;
    __syncthreads();
  }
  if (tid<CSZ) g_Las[(r0+tid)*NH+h]=La[tid];
  __syncthreads();
  if (tid<CSZ) wv[tid]=expf(La[CSZ-1]-La[tid])*dtloc;
  __syncthreads();
  for (int i=tid;i<CSZ*STATE;i+=256){
    int s=i>>6, k=i&63;
    const float* xr=&g_xbc[(size_t)(r0+s)*CONVN];
    Xs[s][k]=xr[h*HDIM+k];
    Bw[s][k]=xr[DINN+k]*wv[s];
  }
  __syncthreads();
  int hb=(tid>>4)<<2, sb=(tid&15)<<2;
  float acc[4][4];
  #pragma unroll
  for (int i=0;i<4;i++){ acc[i][0]=0;acc[i][1]=0;acc[i][2]=0;acc[i][3]=0; }
  for (int s=0;s<CSZ;s++){
    float xv[4], bv[4];
    #pragma unroll
    for (int i=0;i<4;i++) xv[i]=Xs[s][hb+i];
    #pragma unroll
    for (int j=0;j<4;j++) bv[j]=Bw[s][sb+j];
    #pragma unroll
    for (int i=0;i<4;i++)
      #pragma unroll
      for (int j=0;j<4;j++) acc[i][j]+=xv[i]*bv[j];
  }
  float* Hg=&g_Hc[(size_t)bid*HDIM*STATE];
  #pragma unroll
  for (int i=0;i<4;i++)
    #pragma unroll
    for (int j=0;j<4;j++)
      Hg[(hb+i)*STATE + sb+j]=acc[i][j];
}

// ---------------- carry: 128 blocks ----------------
__global__ void carry_kernel(){
  int bh=blockIdx.x>>3;
  int off=(blockIdx.x&7)*512 + threadIdx.x;
  int b=bh>>3, h=bh&7;
  size_t base0=(size_t)(bh*NCH)*HDIM*STATE;
  float hr=0.f;
  float nxt=g_Hc[base0+off];
  for (int c=0;c<NCH;c++){
    float Lend=g_Las[(b*QN + c*CSZ + CSZ-1)*NH + h];
    float f=expf(Lend);
    float cur=nxt;
    if (c+1<NCH) nxt=g_Hc[base0+(size_t)(c+1)*HDIM*STATE+off];
    g_Hin[base0+(size_t)c*HDIM*STATE+off]=hr;
    hr=f*hr+cur;
  }
}

// ---------------- fully fused P + y_intra + y_inter ----------------
__global__ void pyfull_kernel(const float* __restrict__ Dh){
  __shared__ float S1[CSZ][STATE+1];
  __shared__ float S2[CSZ][STATE+1];
  __shared__ float La[CSZ], dtv[CSZ];
  int bid=blockIdx.x;
  int c=bid%NCH, h=(bid/NCH)%NH, b=bid/(NCH*NH);
  int tid=threadIdx.x;
  int r0=b*QN + c*CSZ;
  if (tid<CSZ){ La[tid]=g_Las[(r0+tid)*NH+h]; dtv[tid]=g_dts[(r0+tid)*NH+h]; }
  for (int i=tid;i<CSZ*STATE;i+=256){
    int s=i>>6, st=i&63;
    const float* xr=&g_xbc[(size_t)(r0+s)*CONVN];
    S1[s][st]=xr[DINN+st];
    S2[s][st]=xr[DINN+STATE+st];
  }
  __syncthreads();
  int tb=(tid>>4)<<2, sb=(tid&15)<<2;
  float acc[4][4];
  #pragma unroll
  for (int i=0;i<4;i++){ acc[i][0]=0;acc[i][1]=0;acc[i][2]=0;acc[i][3]=0; }
  for (int k=0;k<STATE;k++){
    float cv[4], bv[4];
    #pragma unroll
    for (int i=0;i<4;i++) cv[i]=S2[tb+i][k];
    #pragma unroll
    for (int j=0;j<4;j++) bv[j]=S1[sb+j][k];
    #pragma unroll
    for (int i=0;i<4;i++)
      #pragma unroll
      for (int j=0;j<4;j++) acc[i][j]+=cv[i]*bv[j];
  }
  float Pv[4][4];
  #pragma unroll
  for (int i=0;i<4;i++){
    int t=tb+i;
    #pragma unroll
    for (int j=0;j<4;j++){
      int s=sb+j;
      Pv[i][j]=(s<=t)? expf(La[t]-La[s])*dtv[s]*acc[i][j] : 0.f;
    }
  }
  __syncthreads();
  const float* Hg=&g_Hin[(size_t)bid*HDIM*STATE];
  for (int i=tid;i<HDIM*STATE;i+=256) S1[i>>6][i&63]=Hg[i];
  __syncthreads();
  float y2[4][4];
  #pragma unroll
  for (int i=0;i<4;i++){ y2[i][0]=0;y2[i][1]=0;y2[i][2]=0;y2[i][3]=0; }
  for (int k=0;k<STATE;k++){
    float cv[4], hv[4];
    #pragma unroll
    for (int i=0;i<4;i++) cv[i]=S2[tb+i][k];
    #pragma unroll
    for (int j=0;j<4;j++) hv[j]=S1[sb+j][k];
    #pragma unroll
    for (int i=0;i<4;i++)
      #pragma unroll
      for (int j=0;j<4;j++) y2[i][j]+=cv[i]*hv[j];
  }
  __syncthreads();
  #pragma unroll
  for (int i=0;i<4;i++)
    #pragma unroll
    for (int j=0;j<4;j++) S2[tb+i][sb+j]=Pv[i][j];
  for (int i=tid;i<CSZ*HDIM;i+=256){
    int s=i>>6,k=i&63;
    S1[s][k]=g_xbc[(size_t)(r0+s)*CONVN + h*HDIM + k];
  }
  __syncthreads();
  int hb=sb;
  float y1[4][4];
  #pragma unroll
  for (int i=0;i<4;i++){ y1[i][0]=0;y1[i][1]=0;y1[i][2]=0;y1[i][3]=0; }
  for (int s=0;s<CSZ;s++){
    float pv[4], xv[4];
    #pragma unroll
    for (int i=0;i<4;i++) pv[i]=S2[tb+i][s];
    #pragma unroll
    for (int j=0;j<4;j++) xv[j]=S1[s][hb+j];
    #pragma unroll
    for (int i=0;i<4;i++)
      #pragma unroll
      for (int j=0;j<4;j++) y1[i][j]+=pv[i]*xv[j];
  }
  float dh=Dh[h];
  #pragma unroll
  for (int i=0;i<4;i++){
    int t=tb+i;
    float f=expf(La[t]);
    #pragma unroll
    for (int j=0;j<4;j++)
      g_y[(size_t)(r0+t)*DINN + h*HDIM + hb+j] = y1[i][j] + dh*S1[t][hb+j] + f*y2[i][j];
  }
}

// ---------------- warp-per-row gated RMSNorm over 512 ----------------
__global__ void gate_rmsw_kernel(const float* __restrict__ rmsw){
  int row=blockIdx.x*8 + (threadIdx.x>>5), lane=threadIdx.x&31;
  const float4* y4=(const float4*)g_y;
  const float4* p4=(const float4*)g_proj;
  const float4* w4=(const float4*)rmsw;
  float4 gg[4];
  float ssum=0.f;
  #pragma unroll
  for (int i=0;i<4;i++){
    float4 y=y4[(size_t)row*128 + i*32 + lane];
    float4 z=p4[(size_t)row*(NPROJN/4) + i*32 + lane];
    gg[i].x=y.x*(z.x*sigmoidf_(z.x));
    gg[i].y=y.y*(z.y*sigmoidf_(z.y));
    gg[i].z=y.z*(z.z*sigmoidf_(z.z));
    gg[i].w=y.w*(z.w*sigmoidf_(z.w));
    ssum+=gg[i].x*gg[i].x+gg[i].y*gg[i].y+gg[i].z*gg[i].z+gg[i].w*gg[i].w;
  }
  ssum=warpSum(ssum);
  float r=rsqrtf(ssum*(1.f/DINN)+1e-5f);
  float4* o4=(float4*)g_gated;
  #pragma unroll
  for (int i=0;i<4;i++){
    float4 w=w4[i*32+lane];
    o4[(size_t)row*128 + i*32 + lane]=make_float4(gg[i].x*r*w.x, gg[i].y*r*w.y,
                                                  gg[i].z*r*w.z, gg[i].w*r*w.w);
  }
}

// ---------------- warp-per-row unsort + average + residual + LN ----------------
__global__ void merge_lnw_kernel(){
  int q=blockIdx.x*8 + (threadIdx.x>>5), lane=threadIdx.x&31;
  int i0=g_inv[q], i1=g_inv[QN+q];
  const float4* x4=(const float4*)g_x;
  const float4* s4=(const float4*)g_ssmout;
  float4 v0=x4[q*64+lane], v1=x4[q*64+32+lane];
  float4 a0=s4[(size_t)i0*64+lane], a1=s4[(size_t)i0*64+32+lane];
  float4 b0=s4[(size_t)(QN+i1)*64+lane], b1=s4[(size_t)(QN+i1)*64+32+lane];
  v0.x+=0.5f*(a0.x+b0.x); v0.y+=0.5f*(a0.y+b0.y);
  v0.z+=0.5f*(a0.z+b0.z); v0.w+=0.5f*(a0.w+b0.w);
  v1.x+=0.5f*(a1.x+b1.x); v1.y+=0.5f*(a1.y+b1.y);
  v1.z+=0.5f*(a1.z+b1.z); v1.w+=0.5f*(a1.w+b1.w);
  float s=warpSum(v0.x+v0.y+v0.z+v0.w+v1.x+v1.y+v1.z+v1.w);
  float mean=s*(1.f/DM);
  float d0x=v0.x-mean,d0y=v0.y-mean,d0z=v0.z-mean,d0w=v0.w-mean;
  float d1x=v1.x-mean,d1y=v1.y-mean,d1z=v1.z-mean,d1w=v1.w-mean;
  float vs=warpSum(d0x*d0x+d0y*d0y+d0z*d0z+d0w*d0w+d1x*d1x+d1y*d1y+d1z*d1z+d1w*d1w);
  float r=rsqrtf(vs*(1.f/DM)+1e-5f);
  float4* o4=(float4*)g_x;
  o4[q*64+lane]   =make_float4(d0x*r,d0y*r,d0z*r,d0w*r);
  o4[q*64+32+lane]=make_float4(d1x*r,d1y*r,d1z*r,d1w*r);
}

// =====================================================================
extern "C" void kernel_launch(void* const* d_in, const int* in_sizes, int n_in,
                              void* d_out, int out_size){
  const float* query      = (const float*)d_in[0];
  const float* query_pos  = (const float*)d_in[1];
  const float* inst_feats = (const float*)d_in[2];
  const float* sp_coords  = (const float*)d_in[3];
  const float* w_q  = (const float*)d_in[4];
  const float* w_v  = (const float*)d_in[5];
  const float* w_o  = (const float*)d_in[6];
  const float* w_k  = (const float*)d_in[7];
  const float* w_b  = (const float*)d_in[8];
  const float* Win  = (const float*)d_in[9];
  const float* Wconv= (const float*)d_in[10];
  const float* bconv= (const float*)d_in[11];
  const float* Alog = (const float*)d_in[12];
  const float* Dh   = (const float*)d_in[13];
  const float* dtb  = (const float*)d_in[14];
  const float* rmsw = (const float*)d_in[15];
  const float* Wout = (const float*)d_in[16];
  const float* fw1  = (const float*)d_in[17];
  const float* fb1  = (const float*)d_in[18];
  const float* fw2  = (const float*)d_in[19];
  const float* fb2  = (const float*)d_in[20];
  const int*   order= (const int*)  d_in[21];
  float* out = (float*)d_out;

  float *pq,*pfbar,*pvbar,*ptmp,*px,*pxs,*pproj,*pgated,*pssm,*pffnh;
  cudaGetSymbolAddress((void**)&pq,    g_q);
  cudaGetSymbolAddress((void**)&pfbar, g_fbar);
  cudaGetSymbolAddress((void**)&pvbar, g_vbar);
  cudaGetSymbolAddress((void**)&ptmp,  g_tmp);
  cudaGetSymbolAddress((void**)&px,    g_x);
  cudaGetSymbolAddress((void**)&pxs,   g_xs);
  cudaGetSymbolAddress((void**)&pproj, g_proj);
  cudaGetSymbolAddress((void**)&pgated,g_gated);
  cudaGetSymbolAddress((void**)&pssm,  g_ssmout);
  cudaGetSymbolAddress((void**)&pffnh, g_ffnh);

  auto gridS=[](int m,int n){ return dim3((unsigned)(n/32),(unsigned)(m/64)); };
  auto gridB=[](int m,int n){ return dim3((unsigned)((n+63)/64),(unsigned)(m/128)); };

  // --- stage 1 (launch #4 = wv GEMM for the profiler) ---
  knn_kernel<<<QN/8,256>>>(query_pos, sp_coords, order);
  tgemm_kernel<64,32,16,16,256,5><<<gridS(QN,DM),256>>>(query, w_q, nullptr, nullptr, pq, QN, DM, DM, 0);
  mixbar2_kernel<<<QN/8,256>>>(w_k, w_b, inst_feats);
  tgemm_kernel<64,32,16,16,256,5><<<gridS(QN,DM),256>>>(pfbar, w_v, nullptr, pq, pvbar, QN, DM, DM, 0);
  tgemm_kernel<64,32,16,16,256,5><<<gridS(QN,DM),256>>>(pvbar, w_o, nullptr, nullptr, ptmp, QN, DM, DM, 0);
  lnw_kernel<<<QN/8,256>>>(px, ptmp, query);

  // --- stage 2: two Mamba2 layers ---
  for (int l=0;l<2;l++){
    lnserw_kernel<<<2*QN/8,256>>>(order);
    tgemm_kernel<128,64,32,32,256,3><<<gridB(2*QN,NPROJN),256>>>(pxs,
        Win + (size_t)l*NPROJN*DM, nullptr, nullptr, pproj, 2*QN, NPROJN, DM, 0);
    conv8_kernel<<<(2*(QN/8)*160)/256,256>>>(Wconv + (size_t)l*CONVN*4, bconv + (size_t)l*CONVN);
    chunkH_kernel<<<2*NH*NCH,256>>>(Alog + l*NH, dtb + l*NH);
    carry_kernel<<<2*NH*8,512>>>();
    pyfull_kernel<<<2*NH*NCH,256>>>(Dh + l*NH);
    gate_rmsw_kernel<<<2*QN/8,256>>>(rmsw + (size_t)l*DINN);
    tgemm_kernel<64,32,16,16,256,5><<<gridS(2*QN,DM),256>>>(pgated,
        Wout + (size_t)l*DM*DINN, nullptr, nullptr, pssm, 2*QN, DM, DINN, 0);
    merge_lnw_kernel<<<QN/8,256>>>();
  }

  // --- stage 3: FFN + final LN ---
  tgemm_kernel<128,64,32,32,256,3><<<gridB(QN,HIDN),256>>>(px, fw1, fb1, nullptr, pffnh, QN, HIDN, DM, 1);
  tgemm_kernel<64,32,16,16,256,5><<<gridS(QN,DM),256>>>(pffnh, fw2, fb2, nullptr, ptmp, QN, DM, HIDN, 0);
  lnw_kernel<<<QN/8,256>>>(out, ptmp, px);
}

// round 14
// speedup vs baseline: 1.0946x; 1.0563x over previous
#include <cuda_runtime.h>
#include <math.h>
#include <stdint.h>

#define QN 2048
#define NPTS 32768
#define DM 256
#define KNN 8
#define NH 8
#define HDIM 64
#define STATE 64
#define DINN 512
#define CONVN 640
#define NPROJN 1160
#define HIDN 1024
#define CSZ 64
#define NCH 32
#define PAD 76

// ---------------- scratch ----------------
__device__ float g_q[QN*DM];
__device__ float g_fbar[QN*DM];
__device__ float g_vbar[QN*DM];
__device__ float g_x[QN*DM];
__device__ float g_tmp[QN*DM];
__device__ int   g_idx[QN*KNN];
__device__ int   g_inv[2*QN];
__device__ float g_xs[2*QN*DM];
__device__ float g_proj[2*QN*NPROJN];
__device__ float g_xbc[2*QN*CONVN];
__device__ float g_dts[2*QN*NH];
__device__ float g_Las[2*QN*NH];
__device__ float g_Hc[2*NH*NCH*HDIM*STATE];
__device__ float g_Hin[2*NH*NCH*HDIM*STATE];
__device__ float g_y[2*QN*DINN];
__device__ float g_gated[2*QN*DINN];
__device__ float g_ssmout[2*QN*DM];
__device__ float g_ffnh[QN*HIDN];

__device__ __forceinline__ float sigmoidf_(float x){ return 1.f/(1.f+expf(-x)); }
__device__ __forceinline__ float warpSum(float v){
  #pragma unroll
  for (int o=16;o;o>>=1) v += __shfl_xor_sync(0xffffffffu, v, o);
  return v;
}
__device__ __forceinline__ uint32_t fu(float x){ return __float_as_uint(x); }
__device__ __forceinline__ void mma_tf32(float* d, uint32_t a0,uint32_t a1,uint32_t a2,uint32_t a3,
                                         uint32_t b0,uint32_t b1){
  asm volatile(
    "mma.sync.aligned.m16n8k8.row.col.f32.tf32.tf32.f32 "
    "{%0,%1,%2,%3}, {%4,%5,%6,%7}, {%8,%9}, {%0,%1,%2,%3};"
    : "+f"(d[0]),"+f"(d[1]),"+f"(d[2]),"+f"(d[3])
    : "r"(a0),"r"(a1),"r"(a2),"r"(a3),"r"(b0),"r"(b1));
}
__device__ __forceinline__ void cpa16(uint32_t s, const float* g, bool v){
  int sz = v?16:0;
  asm volatile("cp.async.cg.shared.global [%0], [%1], 16, %2;" :: "r"(s), "l"(g), "r"(sz));
}

// ---------------- KNN (+ fused inv), float4 tiles with precomputed norms ----------------
#define TPTS 2048
__global__ void knn_kernel(const float* __restrict__ qpos, const float* __restrict__ spos,
                           const int* __restrict__ order){
  __shared__ float4 sp[TPTS];
  {
    int id=blockIdx.x*256+threadIdx.x;
    if (id<2*QN) g_inv[(id/QN)*QN + order[id]] = id%QN;
  }
  int warp = threadIdx.x>>5, lane = threadIdx.x&31;
  int q = blockIdx.x*8 + warp;
  float qx=qpos[q*3+0], qy=qpos[q*3+1], qz=qpos[q*3+2];
  float qq = qx*qx+qy*qy+qz*qz;
  float bd[8]; int bi[8];
  #pragma unroll
  for (int j=0;j<8;j++){ bd[j]=3.0e38f; bi[j]=0x7fffffff; }
  for (int tile=0;tile<NPTS/TPTS;tile++){
    __syncthreads();
    for (int i=threadIdx.x;i<TPTS;i+=256){
      const float* p=&spos[(size_t)(tile*TPTS+i)*3];
      float sx=p[0], sy=p[1], sz=p[2];
      float ss=sx*sx+sy*sy+sz*sz;
      sp[i]=make_float4(sx,sy,sz,ss);
    }
    __syncthreads();
    for (int p=lane;p<TPTS;p+=32){
      float4 s4=sp[p];
      float dot = qx*s4.x+qy*s4.y+qz*s4.z;
      float d2 = qq + s4.w - 2.f*dot;
      if (d2 < bd[7]){
        bd[7]=d2; bi[7]=tile*TPTS+p;
        for (int j=7;j>0;j--){
          if (bd[j]<bd[j-1]){ float td=bd[j];bd[j]=bd[j-1];bd[j-1]=td;
                              int ti=bi[j];bi[j]=bi[j-1];bi[j-1]=ti; }
          else break;
        }
      }
    }
  }
  for (int off=16;off;off>>=1){
    float od[8]; int oi[8];
    #pragma unroll
    for (int j=0;j<8;j++){
      od[j]=__shfl_xor_sync(0xffffffffu,bd[j],off);
      oi[j]=__shfl_xor_sync(0xffffffffu,bi[j],off);
    }
    float nd[8]; int ni[8]; int a=0,c=0;
    for (int t=0;t<8;t++){
      bool mine;
      if (a>=8) mine=false;
      else if (c>=8) mine=true;
      else mine = (bd[a]<od[c]) || (bd[a]==od[c] && bi[a]<=oi[c]);
      if (mine){ nd[t]=bd[a];ni[t]=bi[a];a++; } else { nd[t]=od[c];ni[t]=oi[c];c++; }
    }
    for (int j=0;j<8;j++){ bd[j]=nd[j]; bi[j]=ni[j]; }
  }
  if (lane==0){
    #pragma unroll
    for (int j=0;j<8;j++) g_idx[q*8+j]=bi[j];
  }
}

// ---------------- tf32 GEMM, cp.async S-stage + fragment double buffering ----------------
template<int TBM_, int TBN_, int WM, int WN, int NTHR, int S>
__global__ void __launch_bounds__(NTHR) tgemm_kernel(
    const float* __restrict__ A, const float* __restrict__ B,
    const float* __restrict__ bias, const float* __restrict__ emul,
    float* __restrict__ Cmat, int M, int Nn, int Kk, int act){
  constexpr int MW = TBM_/WM;
  constexpr int MI = WM/16, NI = WN/8;
  constexpr int ROWS = TBM_+TBN_;
  constexpr int SLOTS = ROWS*4;
  constexpr int CNT = (SLOTS+NTHR-1)/NTHR;
  __shared__ float Sm[S][ROWS][20];
  int tid=threadIdx.x, warp=tid>>5, lane=tid&31;
  int wm=(warp%MW)*WM, wn=(warp/MW)*WN;
  int g=lane>>2, tig=lane&3;
  int row0=blockIdx.y*TBM_, col0=blockIdx.x*TBN_;

  float acc[MI][NI][4];
  #pragma unroll
  for (int mi=0;mi<MI;mi++)
    #pragma unroll
    for (int ni=0;ni<NI;ni++)
      #pragma unroll
      for (int r=0;r<4;r++) acc[mi][ni][r]=0.f;

  const float* gp[CNT]; uint32_t so[CNT]; bool val[CNT]; bool actv[CNT];
  #pragma unroll
  for (int i=0;i<CNT;i++){
    int idx=tid+i*NTHR;
    actv[i]=(idx<SLOTS);
    int idc = actv[i]? idx : 0;
    int r=idc>>2, c=(idc&3)<<2;
    if (r<TBM_){ gp[i]=A+(size_t)(row0+r)*Kk+c; val[i]=true; }
    else { int rb=r-TBM_; gp[i]=B+(size_t)(col0+rb)*Kk+c; val[i]=(col0+rb)<Nn; }
    so[i]=(uint32_t)__cvta_generic_to_shared(&Sm[0][r][c]);
  }
  constexpr uint32_t STGB=ROWS*20*4;
  auto issue=[&](int stage, int k0){
    #pragma unroll
    for (int i=0;i<CNT;i++)
      if (actv[i]) cpa16(so[i]+stage*STGB, gp[i]+k0, val[i]);
  };

  int KT=Kk>>4;
  #pragma unroll
  for (int s=0;s<S-1;s++){
    if (s<KT) issue(s, s<<4);
    asm volatile("cp.async.commit_group;" ::: "memory");
  }

  int stage=0;
  for (int kt=0;kt<KT;kt++){
    asm volatile("cp.async.wait_group %0;" :: "n"(S-2) : "memory");
    __syncthreads();
    int p=stage;
    uint32_t af0[MI][4], bf0[NI][2];
    #pragma unroll
    for (int mi=0;mi<MI;mi++){
      int m=wm+mi*16+g;
      af0[mi][0]=fu(Sm[p][m  ][tig  ]);
      af0[mi][1]=fu(Sm[p][m+8][tig  ]);
      af0[mi][2]=fu(Sm[p][m  ][tig+4]);
      af0[mi][3]=fu(Sm[p][m+8][tig+4]);
    }
    #pragma unroll
    for (int ni=0;ni<NI;ni++){
      int n=TBM_+wn+ni*8+g;
      bf0[ni][0]=fu(Sm[p][n][tig  ]);
      bf0[ni][1]=fu(Sm[p][n][tig+4]);
    }
    int nt=kt+S-1;
    if (nt<KT) issue(nt%S, nt<<4);
    asm volatile("cp.async.commit_group;" ::: "memory");
    uint32_t af1[MI][4], bf1[NI][2];
    #pragma unroll
    for (int mi=0;mi<MI;mi++){
      int m=wm+mi*16+g;
      af1[mi][0]=fu(Sm[p][m  ][8+tig  ]);
      af1[mi][1]=fu(Sm[p][m+8][8+tig  ]);
      af1[mi][2]=fu(Sm[p][m  ][8+tig+4]);
      af1[mi][3]=fu(Sm[p][m+8][8+tig+4]);
    }
    #pragma unroll
    for (int ni=0;ni<NI;ni++){
      int n=TBM_+wn+ni*8+g;
      bf1[ni][0]=fu(Sm[p][n][8+tig  ]);
      bf1[ni][1]=fu(Sm[p][n][8+tig+4]);
    }
    #pragma unroll
    for (int mi=0;mi<MI;mi++)
      #pragma unroll
      for (int ni=0;ni<NI;ni++)
        mma_tf32(acc[mi][ni], af0[mi][0],af0[mi][1],af0[mi][2],af0[mi][3],
                 bf0[ni][0],bf0[ni][1]);
    #pragma unroll
    for (int mi=0;mi<MI;mi++)
      #pragma unroll
      for (int ni=0;ni<NI;ni++)
        mma_tf32(acc[mi][ni], af1[mi][0],af1[mi][1],af1[mi][2],af1[mi][3],
                 bf1[ni][0],bf1[ni][1]);
    stage = (stage+1==S)? 0 : stage+1;
  }
  #pragma unroll
  for (int mi=0;mi<MI;mi++){
    int r=row0+wm+mi*16+g;
    #pragma unroll
    for (int ni=0;ni<NI;ni++){
      int c=col0+wn+ni*8+2*tig;
      if (c+1<Nn){
        #pragma unroll
        for (int half=0;half<2;half++){
          int rr=r+half*8;
          float v0=acc[mi][ni][half*2+0], v1=acc[mi][ni][half*2+1];
          if (emul){ v0*=emul[(size_t)rr*Nn+c]; v1*=emul[(size_t)rr*Nn+c+1]; }
          if (bias){ v0+=bias[c]; v1+=bias[c+1]; }
          if (act==1){
            v0=0.5f*v0*(1.f+erff(v0*0.70710678118654752f));
            v1=0.5f*v1*(1.f+erff(v1*0.70710678118654752f));
          }
          *(float2*)&Cmat[(size_t)rr*Nn+c]=make_float2(v0,v1);
        }
      }
    }
  }
}

// ---------------- mixbar: warp per query ----------------
__global__ void mixbar2_kernel(const float* __restrict__ wk, const float* __restrict__ wb,
                               const float* __restrict__ feats){
  int warp=threadIdx.x>>5, lane=threadIdx.x&31;
  int q=blockIdx.x*8+warp;
  const float4* q4=(const float4*)g_q;
  float4 qa=q4[q*64+lane], qb=q4[q*64+32+lane];
  const float4* w4=(const float4*)wk;
  float logit[8];
  #pragma unroll
  for (int k=0;k<8;k++){
    float4 wa=w4[k*64+lane], wb4=w4[k*64+32+lane];
    float p=qa.x*wa.x+qa.y*wa.y+qa.z*wa.z+qa.w*wa.w
           +qb.x*wb4.x+qb.y*wb4.y+qb.z*wb4.z+qb.w*wb4.w;
    logit[k]=warpSum(p)+wb[k];
  }
  float m=logit[0];
  #pragma unroll
  for (int k=1;k<8;k++) m=fmaxf(m,logit[k]);
  float s=0.f; float kw[8];
  #pragma unroll
  for (int k=0;k<8;k++){ kw[k]=expf(logit[k]-m); s+=kw[k]; }
  float inv=1.f/s;
  const float4* f4=(const float4*)feats;
  float4 acc0=make_float4(0,0,0,0), acc1=make_float4(0,0,0,0);
  #pragma unroll
  for (int k=0;k<8;k++){
    float w=kw[k]*inv;
    int idx=g_idx[q*8+k];
    float4 fa=f4[(size_t)idx*64+lane], fb=f4[(size_t)idx*64+32+lane];
    acc0.x+=w*fa.x; acc0.y+=w*fa.y; acc0.z+=w*fa.z; acc0.w+=w*fa.w;
    acc1.x+=w*fb.x; acc1.y+=w*fb.y; acc1.z+=w*fb.z; acc1.w+=w*fb.w;
  }
  float4* o4=(float4*)g_fbar;
  o4[q*64+lane]=acc0; o4[q*64+32+lane]=acc1;
}

// ---------------- warp-per-row LayerNorm: out = LN(a + b) ----------------
__global__ void lnw_kernel(float* __restrict__ out, const float* __restrict__ a,
                           const float* __restrict__ b){
  int row=blockIdx.x*8 + (threadIdx.x>>5), lane=threadIdx.x&31;
  const float4* a4=(const float4*)a; const float4* b4=(const float4*)b;
  float4 v0=a4[row*64+lane], v1=a4[row*64+32+lane];
  float4 w0=b4[row*64+lane], w1=b4[row*64+32+lane];
  v0.x+=w0.x;v0.y+=w0.y;v0.z+=w0.z;v0.w+=w0.w;
  v1.x+=w1.x;v1.y+=w1.y;v1.z+=w1.z;v1.w+=w1.w;
  float s=warpSum(v0.x+v0.y+v0.z+v0.w+v1.x+v1.y+v1.z+v1.w);
  float mean=s*(1.f/DM);
  float d0x=v0.x-mean,d0y=v0.y-mean,d0z=v0.z-mean,d0w=v0.w-mean;
  float d1x=v1.x-mean,d1y=v1.y-mean,d1z=v1.z-mean,d1w=v1.w-mean;
  float vs=warpSum(d0x*d0x+d0y*d0y+d0z*d0z+d0w*d0w+d1x*d1x+d1y*d1y+d1z*d1z+d1w*d1w);
  float r=rsqrtf(vs*(1.f/DM)+1e-5f);
  float4* o4=(float4*)out;
  o4[row*64+lane]   =make_float4(d0x*r,d0y*r,d0z*r,d0w*r);
  o4[row*64+32+lane]=make_float4(d1x*r,d1y*r,d1z*r,d1w*r);
}

// ---------------- warp-per-row LN + serialize ----------------
__global__ void lnserw_kernel(const int* __restrict__ order){
  int row=blockIdx.x*8 + (threadIdx.x>>5), lane=threadIdx.x&31;
  int src=order[row];
  const float4* a4=(const float4*)g_x;
  float4 v0=a4[src*64+lane], v1=a4[src*64+32+lane];
  float s=warpSum(v0.x+v0.y+v0.z+v0.w+v1.x+v1.y+v1.z+v1.w);
  float mean=s*(1.f/DM);
  float d0x=v0.x-mean,d0y=v0.y-mean,d0z=v0.z-mean,d0w=v0.w-mean;
  float d1x=v1.x-mean,d1y=v1.y-mean,d1z=v1.z-mean,d1w=v1.w-mean;
  float vs=warpSum(d0x*d0x+d0y*d0y+d0z*d0z+d0w*d0w+d1x*d1x+d1y*d1y+d1z*d1z+d1w*d1w);
  float r=rsqrtf(vs*(1.f/DM)+1e-5f);
  float4* o4=(float4*)g_xs;
  o4[row*64+lane]   =make_float4(d0x*r,d0y*r,d0z*r,d0w*r);
  o4[row*64+32+lane]=make_float4(d1x*r,d1y*r,d1z*r,d1w*r);
}

// ---------------- conv + silu: thread = (b, c4, 8 timesteps) ----------------
__global__ void conv8_kernel(const float* __restrict__ wconv, const float* __restrict__ bconv){
  int id=blockIdx.x*blockDim.x+threadIdx.x;
  int c4=id%160; int t8=(id/160)%(QN/8); int b=id/(160*(QN/8));
  int t0=t8*8;
  const float4* bc4=(const float4*)bconv;
  float4 bias=bc4[c4];
  const float4* w4=(const float4*)wconv;
  float4 w0=w4[c4*4+0], w1=w4[c4*4+1], w2=w4[c4*4+2], w3=w4[c4*4+3];
  const float4* p4=(const float4*)g_proj;
  float4 xv[11];
  #pragma unroll
  for (int i=0;i<11;i++){
    int tt=t0-3+i;
    xv[i] = (tt>=0)? p4[(size_t)(b*QN+tt)*(NPROJN/4) + DINN/4 + c4]
                   : make_float4(0.f,0.f,0.f,0.f);
  }
  float4* ob=(float4*)g_xbc;
  #pragma unroll
  for (int u=0;u<8;u++){
    float4 acc=bias;
    #pragma unroll
    for (int j=0;j<4;j++){
      float4 x=xv[u+j];
      acc.x+=x.x*(&w0.x)[j]; acc.y+=x.y*(&w1.x)[j];
      acc.z+=x.z*(&w2.x)[j]; acc.w+=x.w*(&w3.x)[j];
    }
    acc.x*=sigmoidf_(acc.x); acc.y*=sigmoidf_(acc.y);
    acc.z*=sigmoidf_(acc.z); acc.w*=sigmoidf_(acc.w);
    ob[(size_t)(b*QN+t0+u)*160 + c4]=acc;
  }
}

// ---------------- chunkH: MMA version (Hc = X^T · Bw), pad-76 k-major smem ----------------
__global__ void __launch_bounds__(256) chunkH_kernel(const float* __restrict__ alog,
                                                     const float* __restrict__ dtb){
  __shared__ float Xt[HDIM][PAD];    // Xt[hd][s]
  __shared__ float Bwt[STATE][PAD];  // Bwt[st][s]
  __shared__ float La[CSZ], wv[CSZ];
  int bid=blockIdx.x;
  int c=bid%NCH, h=(bid/NCH)%NH, b=bid/(NCH*NH);
  int tid=threadIdx.x;
  int r0=b*QN + c*CSZ;
  float dtloc=0.f;
  if (tid<CSZ){
    int row=r0+tid;
    float raw = g_proj[(size_t)row*NPROJN + DINN+CONVN + h] + dtb[h];
    dtloc = raw>20.f? raw : log1pf(expf(raw));
    g_dts[row*NH+h]=dtloc;
    float A=-expf(alog[h]);
    La[tid]=dtloc*A;
  }
  __syncthreads();
  for (int o=1;o<CSZ;o<<=1){
    float v=0.f;
    if (tid<CSZ && tid>=o) v=La[tid-o];
    __syncthreads();
    if (tid<CSZ) La[tid]+=v;
    __syncthreads();
  }
  if (tid<CSZ) g_Las[(r0+tid)*NH+h]=La[tid];
  __syncthreads();
  if (tid<CSZ) wv[tid]=expf(La[CSZ-1]-La[tid])*dtloc;
  __syncthreads();
  for (int i=tid;i<CSZ*STATE;i+=256){
    int s=i>>6, k=i&63;
    const float* xr=&g_xbc[(size_t)(r0+s)*CONVN];
    Xt[k][s]=xr[h*HDIM+k];
    Bwt[k][s]=xr[DINN+k]*wv[s];
  }
  __syncthreads();
  int warp=tid>>5, lane=tid&31, g=lane>>2, tig=lane&3;
  int wm=(warp&3)*16;
  int wn0=(warp>>2)*16;
  float acc[2][2][4];
  #pragma unroll
  for (int r=0;r<2;r++)
    #pragma unroll
    for (int q8=0;q8<2;q8++)
      #pragma unroll
      for (int e=0;e<4;e++) acc[r][q8][e]=0.f;
  for (int ks=0;ks<CSZ;ks+=8){
    uint32_t a0=fu(Xt[wm+g][ks+tig]),   a1=fu(Xt[wm+8+g][ks+tig]);
    uint32_t a2=fu(Xt[wm+g][ks+tig+4]), a3=fu(Xt[wm+8+g][ks+tig+4]);
    #pragma unroll
    for (int r=0;r<2;r++){
      int nb=wn0+r*32;
      #pragma unroll
      for (int q8=0;q8<2;q8++){
        uint32_t b0=fu(Bwt[nb+q8*8+g][ks+tig]);
        uint32_t b1=fu(Bwt[nb+q8*8+g][ks+tig+4]);
        mma_tf32(acc[r][q8], a0,a1,a2,a3, b0,b1);
      }
    }
  }
  float* Hg=&g_Hc[(size_t)bid*HDIM*STATE];
  int m0=wm+g, m1=wm+8+g;
  #pragma unroll
  for (int r=0;r<2;r++){
    #pragma unroll
    for (int q8=0;q8<2;q8++){
      int cc=wn0+r*32+q8*8+2*tig;
      Hg[m0*STATE+cc  ]=acc[r][q8][0];
      Hg[m0*STATE+cc+1]=acc[r][q8][1];
      Hg[m1*STATE+cc  ]=acc[r][q8][2];
      Hg[m1*STATE+cc+1]=acc[r][q8][3];
    }
  }
}

// ---------------- carry: 128 blocks ----------------
__global__ void carry_kernel(){
  int bh=blockIdx.x>>3;
  int off=(blockIdx.x&7)*512 + threadIdx.x;
  int b=bh>>3, h=bh&7;
  size_t base0=(size_t)(bh*NCH)*HDIM*STATE;
  float hr=0.f;
  float nxt=g_Hc[base0+off];
  for (int c=0;c<NCH;c++){
    float Lend=g_Las[(b*QN + c*CSZ + CSZ-1)*NH + h];
    float f=expf(Lend);
    float cur=nxt;
    if (c+1<NCH) nxt=g_Hc[base0+(size_t)(c+1)*HDIM*STATE+off];
    g_Hin[base0+(size_t)c*HDIM*STATE+off]=hr;
    hr=f*hr+cur;
  }
}

// ---------------- pyfull: 3-phase MMA (P=C·B^T masked; y2=C·Hi^T; y1=P·X) ----------------
#define PY_SMEM (3*64*PAD*4)
__global__ void __launch_bounds__(256) pyfull_kernel(const float* __restrict__ Dh){
  extern __shared__ float dyn[];
  float (*SA)[PAD]=(float(*)[PAD])dyn;              // Ct, later Xt
  float (*SB)[PAD]=(float(*)[PAD])(dyn+64*PAD);     // Bk, later Hik
  float (*SP)[PAD]=(float(*)[PAD])(dyn+2*64*PAD);   // Pm
  __shared__ float La[CSZ], dtv[CSZ];
  int bid=blockIdx.x;
  int c=bid%NCH, h=(bid/NCH)%NH, b=bid/(NCH*NH);
  int tid=threadIdx.x;
  int r0=b*QN + c*CSZ;
  if (tid<CSZ){ La[tid]=g_Las[(r0+tid)*NH+h]; dtv[tid]=g_dts[(r0+tid)*NH+h]; }
  for (int i=tid;i<CSZ*STATE;i+=256){
    int t=i>>6, k=i&63;
    const float* xr=&g_xbc[(size_t)(r0+t)*CONVN];
    SA[t][k]=xr[DINN+STATE+k];   // C[t][k]
    SB[t][k]=xr[DINN+k];         // B[s][k]  (row index is s here)
  }
  __syncthreads();
  int warp=tid>>5, lane=tid&31, g=lane>>2, tig=lane&3;
  int wm=(warp&3)*16;
  int wn0=(warp>>2)*16;
  int m0=wm+g, m1=wm+8+g;
  // ---- phase 1: P = C · B^T (m=t, n=s, k=state) ----
  float accp[2][2][4];
  #pragma unroll
  for (int r=0;r<2;r++)
    #pragma unroll
    for (int q8=0;q8<2;q8++)
      #pragma unroll
      for (int e=0;e<4;e++) accp[r][q8][e]=0.f;
  for (int ks=0;ks<STATE;ks+=8){
    uint32_t a0=fu(SA[m0][ks+tig]),   a1=fu(SA[m1][ks+tig]);
    uint32_t a2=fu(SA[m0][ks+tig+4]), a3=fu(SA[m1][ks+tig+4]);
    #pragma unroll
    for (int r=0;r<2;r++){
      int nb=wn0+r*32;
      #pragma unroll
      for (int q8=0;q8<2;q8++){
        uint32_t b0=fu(SB[nb+q8*8+g][ks+tig]);
        uint32_t b1=fu(SB[nb+q8*8+g][ks+tig+4]);
        mma_tf32(accp[r][q8], a0,a1,a2,a3, b0,b1);
      }
    }
  }
  float La0=La[m0], La1=La[m1];
  float Pv[2][2][4];
  #pragma unroll
  for (int r=0;r<2;r++){
    #pragma unroll
    for (int q8=0;q8<2;q8++){
      int s0=wn0+r*32+q8*8+2*tig, s1=s0+1;
      Pv[r][q8][0]=(s0<=m0)? expf(La0-La[s0])*dtv[s0]*accp[r][q8][0] : 0.f;
      Pv[r][q8][1]=(s1<=m0)? expf(La0-La[s1])*dtv[s1]*accp[r][q8][1] : 0.f;
      Pv[r][q8][2]=(s0<=m1)? expf(La1-La[s0])*dtv[s0]*accp[r][q8][2] : 0.f;
      Pv[r][q8][3]=(s1<=m1)? expf(La1-La[s1])*dtv[s1]*accp[r][q8][3] : 0.f;
    }
  }
  __syncthreads();   // all p1 smem reads done
  // store P; load Hi over SB
  #pragma unroll
  for (int r=0;r<2;r++){
    #pragma unroll
    for (int q8=0;q8<2;q8++){
      int s0=wn0+r*32+q8*8+2*tig;
      SP[m0][s0  ]=Pv[r][q8][0];
      SP[m0][s0+1]=Pv[r][q8][1];
      SP[m1][s0  ]=Pv[r][q8][2];
      SP[m1][s0+1]=Pv[r][q8][3];
    }
  }
  const float* Hg=&g_Hin[(size_t)bid*HDIM*STATE];
  for (int i=tid;i<HDIM*STATE;i+=256) SB[i>>6][i&63]=Hg[i];
  __syncthreads();
  // ---- phase 2: y2 = C · Hi^T (m=t, n=hd, k=state) ----
  float y2[2][2][4];
  #pragma unroll
  for (int r=0;r<2;r++)
    #pragma unroll
    for (int q8=0;q8<2;q8++)
      #pragma unroll
      for (int e=0;e<4;e++) y2[r][q8][e]=0.f;
  for (int ks=0;ks<STATE;ks+=8){
    uint32_t a0=fu(SA[m0][ks+tig]),   a1=fu(SA[m1][ks+tig]);
    uint32_t a2=fu(SA[m0][ks+tig+4]), a3=fu(SA[m1][ks+tig+4]);
    #pragma unroll
    for (int r=0;r<2;r++){
      int nb=wn0+r*32;
      #pragma unroll
      for (int q8=0;q8<2;q8++){
        uint32_t b0=fu(SB[nb+q8*8+g][ks+tig]);
        uint32_t b1=fu(SB[nb+q8*8+g][ks+tig+4]);
        mma_tf32(y2[r][q8], a0,a1,a2,a3, b0,b1);
      }
    }
  }
  __syncthreads();   // p2 reads of SA done; overwrite SA with Xt
  for (int i=tid;i<CSZ*HDIM;i+=256){
    int s=i>>6, k=i&63;
    SA[k][s]=g_xbc[(size_t)(r0+s)*CONVN + h*HDIM + k];   // Xt[hd][s]
  }
  __syncthreads();
  // ---- phase 3: y1 = P · X (m=t, n=hd, k=s); combine ----
  float y1[2][2][4];
  #pragma unroll
  for (int r=0;r<2;r++)
    #pragma unroll
    for (int q8=0;q8<2;q8++)
      #pragma unroll
      for (int e=0;e<4;e++) y1[r][q8][e]=0.f;
  for (int ks=0;ks<CSZ;ks+=8){
    uint32_t a0=fu(SP[m0][ks+tig]),   a1=fu(SP[m1][ks+tig]);
    uint32_t a2=fu(SP[m0][ks+tig+4]), a3=fu(SP[m1][ks+tig+4]);
    #pragma unroll
    for (int r=0;r<2;r++){
      int nb=wn0+r*32;
      #pragma unroll
      for (int q8=0;q8<2;q8++){
        uint32_t b0=fu(SA[nb+q8*8+g][ks+tig]);
        uint32_t b1=fu(SA[nb+q8*8+g][ks+tig+4]);
        mma_tf32(y1[r][q8], a0,a1,a2,a3, b0,b1);
      }
    }
  }
  float dh=Dh[h];
  float f0=expf(La0), f1=expf(La1);
  #pragma unroll
  for (int r=0;r<2;r++){
    #pragma unroll
    for (int q8=0;q8<2;q8++){
      int hd0=wn0+r*32+q8*8+2*tig, hd1=hd0+1;
      size_t o0=(size_t)(r0+m0)*DINN + h*HDIM;
      size_t o1=(size_t)(r0+m1)*DINN + h*HDIM;
      g_y[o0+hd0]=y1[r][q8][0] + dh*SA[hd0][m0] + f0*y2[r][q8][0];
      g_y[o0+hd1]=y1[r][q8][1] + dh*SA[hd1][m0] + f0*y2[r][q8][1];
      g_y[o1+hd0]=y1[r][q8][2] + dh*SA[hd0][m1] + f1*y2[r][q8][2];
      g_y[o1+hd1]=y1[r][q8][3] + dh*SA[hd1][m1] + f1*y2[r][q8][3];
    }
  }
}

// ---------------- warp-per-row gated RMSNorm over 512 ----------------
__global__ void gate_rmsw_kernel(const float* __restrict__ rmsw){
  int row=blockIdx.x*8 + (threadIdx.x>>5), lane=threadIdx.x&31;
  const float4* y4=(const float4*)g_y;
  const float4* p4=(const float4*)g_proj;
  const float4* w4=(const float4*)rmsw;
  float4 gg[4];
  float ssum=0.f;
  #pragma unroll
  for (int i=0;i<4;i++){
    float4 y=y4[(size_t)row*128 + i*32 + lane];
    float4 z=p4[(size_t)row*(NPROJN/4) + i*32 + lane];
    gg[i].x=y.x*(z.x*sigmoidf_(z.x));
    gg[i].y=y.y*(z.y*sigmoidf_(z.y));
    gg[i].z=y.z*(z.z*sigmoidf_(z.z));
    gg[i].w=y.w*(z.w*sigmoidf_(z.w));
    ssum+=gg[i].x*gg[i].x+gg[i].y*gg[i].y+gg[i].z*gg[i].z+gg[i].w*gg[i].w;
  }
  ssum=warpSum(ssum);
  float r=rsqrtf(ssum*(1.f/DINN)+1e-5f);
  float4* o4=(float4*)g_gated;
  #pragma unroll
  for (int i=0;i<4;i++){
    float4 w=w4[i*32+lane];
    o4[(size_t)row*128 + i*32 + lane]=make_float4(gg[i].x*r*w.x, gg[i].y*r*w.y,
                                                  gg[i].z*r*w.z, gg[i].w*r*w.w);
  }
}

// ---------------- warp-per-row unsort + average + residual + LN ----------------
__global__ void merge_lnw_kernel(){
  int q=blockIdx.x*8 + (threadIdx.x>>5), lane=threadIdx.x&31;
  int i0=g_inv[q], i1=g_inv[QN+q];
  const float4* x4=(const float4*)g_x;
  const float4* s4=(const float4*)g_ssmout;
  float4 v0=x4[q*64+lane], v1=x4[q*64+32+lane];
  float4 a0=s4[(size_t)i0*64+lane], a1=s4[(size_t)i0*64+32+lane];
  float4 b0=s4[(size_t)(QN+i1)*64+lane], b1=s4[(size_t)(QN+i1)*64+32+lane];
  v0.x+=0.5f*(a0.x+b0.x); v0.y+=0.5f*(a0.y+b0.y);
  v0.z+=0.5f*(a0.z+b0.z); v0.w+=0.5f*(a0.w+b0.w);
  v1.x+=0.5f*(a1.x+b1.x); v1.y+=0.5f*(a1.y+b1.y);
  v1.z+=0.5f*(a1.z+b1.z); v1.w+=0.5f*(a1.w+b1.w);
  float s=warpSum(v0.x+v0.y+v0.z+v0.w+v1.x+v1.y+v1.z+v1.w);
  float mean=s*(1.f/DM);
  float d0x=v0.x-mean,d0y=v0.y-mean,d0z=v0.z-mean,d0w=v0.w-mean;
  float d1x=v1.x-mean,d1y=v1.y-mean,d1z=v1.z-mean,d1w=v1.w-mean;
  float vs=warpSum(d0x*d0x+d0y*d0y+d0z*d0z+d0w*d0w+d1x*d1x+d1y*d1y+d1z*d1z+d1w*d1w);
  float r=rsqrtf(vs*(1.f/DM)+1e-5f);
  float4* o4=(float4*)g_x;
  o4[q*64+lane]   =make_float4(d0x*r,d0y*r,d0z*r,d0w*r);
  o4[q*64+32+lane]=make_float4(d1x*r,d1y*r,d1z*r,d1w*r);
}

// =====================================================================
extern "C" void kernel_launch(void* const* d_in, const int* in_sizes, int n_in,
                              void* d_out, int out_size){
  const float* query      = (const float*)d_in[0];
  const float* query_pos  = (const float*)d_in[1];
  const float* inst_feats = (const float*)d_in[2];
  const float* sp_coords  = (const float*)d_in[3];
  const float* w_q  = (const float*)d_in[4];
  const float* w_v  = (const float*)d_in[5];
  const float* w_o  = (const float*)d_in[6];
  const float* w_k  = (const float*)d_in[7];
  const float* w_b  = (const float*)d_in[8];
  const float* Win  = (const float*)d_in[9];
  const float* Wconv= (const float*)d_in[10];
  const float* bconv= (const float*)d_in[11];
  const float* Alog = (const float*)d_in[12];
  const float* Dh   = (const float*)d_in[13];
  const float* dtb  = (const float*)d_in[14];
  const float* rmsw = (const float*)d_in[15];
  const float* Wout = (const float*)d_in[16];
  const float* fw1  = (const float*)d_in[17];
  const float* fb1  = (const float*)d_in[18];
  const float* fw2  = (const float*)d_in[19];
  const float* fb2  = (const float*)d_in[20];
  const int*   order= (const int*)  d_in[21];
  float* out = (float*)d_out;

  float *pq,*pfbar,*pvbar,*ptmp,*px,*pxs,*pproj,*pgated,*pssm,*pffnh;
  cudaGetSymbolAddress((void**)&pq,    g_q);
  cudaGetSymbolAddress((void**)&pfbar, g_fbar);
  cudaGetSymbolAddress((void**)&pvbar, g_vbar);
  cudaGetSymbolAddress((void**)&ptmp,  g_tmp);
  cudaGetSymbolAddress((void**)&px,    g_x);
  cudaGetSymbolAddress((void**)&pxs,   g_xs);
  cudaGetSymbolAddress((void**)&pproj, g_proj);
  cudaGetSymbolAddress((void**)&pgated,g_gated);
  cudaGetSymbolAddress((void**)&pssm,  g_ssmout);
  cudaGetSymbolAddress((void**)&pffnh, g_ffnh);

  static bool attr_done=false;
  if (!attr_done){
    cudaFuncSetAttribute(pyfull_kernel, cudaFuncAttributeMaxDynamicSharedMemorySize, PY_SMEM);
    attr_done=true;
  }

  auto gridS=[](int m,int n){ return dim3((unsigned)(n/32),(unsigned)(m/64)); };
  auto gridB=[](int m,int n){ return dim3((unsigned)((n+63)/64),(unsigned)(m/128)); };

  // --- stage 1 ---
  knn_kernel<<<QN/8,256>>>(query_pos, sp_coords, order);
  tgemm_kernel<64,32,16,16,256,5><<<gridS(QN,DM),256>>>(query, w_q, nullptr, nullptr, pq, QN, DM, DM, 0);
  mixbar2_kernel<<<QN/8,256>>>(w_k, w_b, inst_feats);
  tgemm_kernel<64,32,16,16,256,5><<<gridS(QN,DM),256>>>(pfbar, w_v, nullptr, pq, pvbar, QN, DM, DM, 0);
  tgemm_kernel<64,32,16,16,256,5><<<gridS(QN,DM),256>>>(pvbar, w_o, nullptr, nullptr, ptmp, QN, DM, DM, 0);
  lnw_kernel<<<QN/8,256>>>(px, ptmp, query);

  // --- stage 2: two Mamba2 layers ---
  for (int l=0;l<2;l++){
    lnserw_kernel<<<2*QN/8,256>>>(order);
    tgemm_kernel<128,64,32,32,256,3><<<gridB(2*QN,NPROJN),256>>>(pxs,
        Win + (size_t)l*NPROJN*DM, nullptr, nullptr, pproj, 2*QN, NPROJN, DM, 0);
    conv8_kernel<<<(2*(QN/8)*160)/256,256>>>(Wconv + (size_t)l*CONVN*4, bconv + (size_t)l*CONVN);
    chunkH_kernel<<<2*NH*NCH,256>>>(Alog + l*NH, dtb + l*NH);
    carry_kernel<<<2*NH*8,512>>>();
    pyfull_kernel<<<2*NH*NCH,256,PY_SMEM>>>(Dh + l*NH);
    gate_rmsw_kernel<<<2*QN/8,256>>>(rmsw + (size_t)l*DINN);
    tgemm_kernel<64,32,16,16,256,5><<<gridS(2*QN,DM),256>>>(pgated,
        Wout + (size_t)l*DM*DINN, nullptr, nullptr, pssm, 2*QN, DM, DINN, 0);
    merge_lnw_kernel<<<QN/8,256>>>();
  }

  // --- stage 3: FFN + final LN ---
  tgemm_kernel<128,64,32,32,256,3><<<gridB(QN,HIDN),256>>>(px, fw1, fb1, nullptr, pffnh, QN, HIDN, DM, 1);
  tgemm_kernel<64,32,16,16,256,5><<<gridS(QN,DM),256>>>(pffnh, fw2, fb2, nullptr, ptmp, QN, DM, HIDN, 0);
  lnw_kernel<<<QN/8,256>>>(out, ptmp, px);
}

// round 15
// speedup vs baseline: 1.1081x; 1.0124x over previous
#include <cuda_runtime.h>
#include <math.h>
#include <stdint.h>

#define QN 2048
#define NPTS 32768
#define DM 256
#define KNN 8
#define NH 8
#define HDIM 64
#define STATE 64
#define DINN 512
#define CONVN 640
#define NPROJN 1160
#define HIDN 1024
#define CSZ 64
#define NCH 32
#define PAD 76

// ---------------- scratch ----------------
__device__ float g_q[QN*DM];
__device__ float g_fbar[QN*DM];
__device__ float g_vbar[QN*DM];
__device__ float g_x[QN*DM];
__device__ float g_tmp[QN*DM];
__device__ int   g_idx[QN*KNN];
__device__ int   g_inv[2*QN];
__device__ float g_proj[2*QN*NPROJN];
__device__ float g_xbc[2*QN*CONVN];
__device__ float g_dts[2*QN*NH];
__device__ float g_Las[2*QN*NH];
__device__ float g_Hc[2*NH*NCH*HDIM*STATE];
__device__ float g_Hin[2*NH*NCH*HDIM*STATE];
__device__ float g_y[2*QN*DINN];
__device__ float g_gated[2*QN*DINN];
__device__ float g_ssmout[2*QN*DM];
__device__ float g_ffnh[QN*HIDN];

__device__ __forceinline__ float sigmoidf_(float x){ return 1.f/(1.f+expf(-x)); }
__device__ __forceinline__ float warpSum(float v){
  #pragma unroll
  for (int o=16;o;o>>=1) v += __shfl_xor_sync(0xffffffffu, v, o);
  return v;
}
__device__ __forceinline__ uint32_t fu(float x){ return __float_as_uint(x); }
__device__ __forceinline__ void mma_tf32(float* d, uint32_t a0,uint32_t a1,uint32_t a2,uint32_t a3,
                                         uint32_t b0,uint32_t b1){
  asm volatile(
    "mma.sync.aligned.m16n8k8.row.col.f32.tf32.tf32.f32 "
    "{%0,%1,%2,%3}, {%4,%5,%6,%7}, {%8,%9}, {%0,%1,%2,%3};"
    : "+f"(d[0]),"+f"(d[1]),"+f"(d[2]),"+f"(d[3])
    : "r"(a0),"r"(a1),"r"(a2),"r"(a3),"r"(b0),"r"(b1));
}
__device__ __forceinline__ void cpa16(uint32_t s, const float* g, bool v){
  int sz = v?16:0;
  asm volatile("cp.async.cg.shared.global [%0], [%1], 16, %2;" :: "r"(s), "l"(g), "r"(sz));
}

// ---------------- KNN (+ fused inv), float4 tiles with precomputed norms ----------------
#define TPTS 2048
__global__ void knn_kernel(const float* __restrict__ qpos, const float* __restrict__ spos,
                           const int* __restrict__ order){
  __shared__ float4 sp[TPTS];
  {
    int id=blockIdx.x*256+threadIdx.x;
    if (id<2*QN) g_inv[(id/QN)*QN + order[id]] = id%QN;
  }
  int warp = threadIdx.x>>5, lane = threadIdx.x&31;
  int q = blockIdx.x*8 + warp;
  float qx=qpos[q*3+0], qy=qpos[q*3+1], qz=qpos[q*3+2];
  float qq = qx*qx+qy*qy+qz*qz;
  float bd[8]; int bi[8];
  #pragma unroll
  for (int j=0;j<8;j++){ bd[j]=3.0e38f; bi[j]=0x7fffffff; }
  for (int tile=0;tile<NPTS/TPTS;tile++){
    __syncthreads();
    for (int i=threadIdx.x;i<TPTS;i+=256){
      const float* p=&spos[(size_t)(tile*TPTS+i)*3];
      float sx=p[0], sy=p[1], sz=p[2];
      float ss=sx*sx+sy*sy+sz*sz;
      sp[i]=make_float4(sx,sy,sz,ss);
    }
    __syncthreads();
    for (int p=lane;p<TPTS;p+=32){
      float4 s4=sp[p];
      float dot = qx*s4.x+qy*s4.y+qz*s4.z;
      float d2 = qq + s4.w - 2.f*dot;
      if (d2 < bd[7]){
        bd[7]=d2; bi[7]=tile*TPTS+p;
        for (int j=7;j>0;j--){
          if (bd[j]<bd[j-1]){ float td=bd[j];bd[j]=bd[j-1];bd[j-1]=td;
                              int ti=bi[j];bi[j]=bi[j-1];bi[j-1]=ti; }
          else break;
        }
      }
    }
  }
  for (int off=16;off;off>>=1){
    float od[8]; int oi[8];
    #pragma unroll
    for (int j=0;j<8;j++){
      od[j]=__shfl_xor_sync(0xffffffffu,bd[j],off);
      oi[j]=__shfl_xor_sync(0xffffffffu,bi[j],off);
    }
    float nd[8]; int ni[8]; int a=0,c=0;
    for (int t=0;t<8;t++){
      bool mine;
      if (a>=8) mine=false;
      else if (c>=8) mine=true;
      else mine = (bd[a]<od[c]) || (bd[a]==od[c] && bi[a]<=oi[c]);
      if (mine){ nd[t]=bd[a];ni[t]=bi[a];a++; } else { nd[t]=od[c];ni[t]=oi[c];c++; }
    }
    for (int j=0;j<8;j++){ bd[j]=nd[j]; bi[j]=ni[j]; }
  }
  if (lane==0){
    #pragma unroll
    for (int j=0;j<8;j++) g_idx[q*8+j]=bi[j];
  }
}

// ---------------- tf32 GEMM, cp.async S-stage + fragment double buffering ----------------
// Optional Arows: row-gather indices for A (A row r := A[Arows[row0+r]]).
template<int TBM_, int TBN_, int WM, int WN, int NTHR, int S>
__global__ void __launch_bounds__(NTHR) tgemm_kernel(
    const float* __restrict__ A, const float* __restrict__ B,
    const float* __restrict__ bias, const float* __restrict__ emul,
    const int* __restrict__ Arows,
    float* __restrict__ Cmat, int M, int Nn, int Kk, int act){
  constexpr int MW = TBM_/WM;
  constexpr int MI = WM/16, NI = WN/8;
  constexpr int ROWS = TBM_+TBN_;
  constexpr int SLOTS = ROWS*4;
  constexpr int CNT = (SLOTS+NTHR-1)/NTHR;
  __shared__ float Sm[S][ROWS][20];
  int tid=threadIdx.x, warp=tid>>5, lane=tid&31;
  int wm=(warp%MW)*WM, wn=(warp/MW)*WN;
  int g=lane>>2, tig=lane&3;
  int row0=blockIdx.y*TBM_, col0=blockIdx.x*TBN_;

  float acc[MI][NI][4];
  #pragma unroll
  for (int mi=0;mi<MI;mi++)
    #pragma unroll
    for (int ni=0;ni<NI;ni++)
      #pragma unroll
      for (int r=0;r<4;r++) acc[mi][ni][r]=0.f;

  const float* gp[CNT]; uint32_t so[CNT]; bool val[CNT]; bool actv[CNT];
  #pragma unroll
  for (int i=0;i<CNT;i++){
    int idx=tid+i*NTHR;
    actv[i]=(idx<SLOTS);
    int idc = actv[i]? idx : 0;
    int r=idc>>2, c=(idc&3)<<2;
    if (r<TBM_){
      int ar = Arows? Arows[row0+r] : (row0+r);
      gp[i]=A+(size_t)ar*Kk+c; val[i]=true;
    }
    else { int rb=r-TBM_; gp[i]=B+(size_t)(col0+rb)*Kk+c; val[i]=(col0+rb)<Nn; }
    so[i]=(uint32_t)__cvta_generic_to_shared(&Sm[0][r][c]);
  }
  constexpr uint32_t STGB=ROWS*20*4;
  auto issue=[&](int stage, int k0){
    #pragma unroll
    for (int i=0;i<CNT;i++)
      if (actv[i]) cpa16(so[i]+stage*STGB, gp[i]+k0, val[i]);
  };

  int KT=Kk>>4;
  #pragma unroll
  for (int s=0;s<S-1;s++){
    if (s<KT) issue(s, s<<4);
    asm volatile("cp.async.commit_group;" ::: "memory");
  }

  int stage=0;
  for (int kt=0;kt<KT;kt++){
    asm volatile("cp.async.wait_group %0;" :: "n"(S-2) : "memory");
    __syncthreads();
    int p=stage;
    uint32_t af0[MI][4], bf0[NI][2];
    #pragma unroll
    for (int mi=0;mi<MI;mi++){
      int m=wm+mi*16+g;
      af0[mi][0]=fu(Sm[p][m  ][tig  ]);
      af0[mi][1]=fu(Sm[p][m+8][tig  ]);
      af0[mi][2]=fu(Sm[p][m  ][tig+4]);
      af0[mi][3]=fu(Sm[p][m+8][tig+4]);
    }
    #pragma unroll
    for (int ni=0;ni<NI;ni++){
      int n=TBM_+wn+ni*8+g;
      bf0[ni][0]=fu(Sm[p][n][tig  ]);
      bf0[ni][1]=fu(Sm[p][n][tig+4]);
    }
    int nt=kt+S-1;
    if (nt<KT) issue(nt%S, nt<<4);
    asm volatile("cp.async.commit_group;" ::: "memory");
    uint32_t af1[MI][4], bf1[NI][2];
    #pragma unroll
    for (int mi=0;mi<MI;mi++){
      int m=wm+mi*16+g;
      af1[mi][0]=fu(Sm[p][m  ][8+tig  ]);
      af1[mi][1]=fu(Sm[p][m+8][8+tig  ]);
      af1[mi][2]=fu(Sm[p][m  ][8+tig+4]);
      af1[mi][3]=fu(Sm[p][m+8][8+tig+4]);
    }
    #pragma unroll
    for (int ni=0;ni<NI;ni++){
      int n=TBM_+wn+ni*8+g;
      bf1[ni][0]=fu(Sm[p][n][8+tig  ]);
      bf1[ni][1]=fu(Sm[p][n][8+tig+4]);
    }
    #pragma unroll
    for (int mi=0;mi<MI;mi++)
      #pragma unroll
      for (int ni=0;ni<NI;ni++)
        mma_tf32(acc[mi][ni], af0[mi][0],af0[mi][1],af0[mi][2],af0[mi][3],
                 bf0[ni][0],bf0[ni][1]);
    #pragma unroll
    for (int mi=0;mi<MI;mi++)
      #pragma unroll
      for (int ni=0;ni<NI;ni++)
        mma_tf32(acc[mi][ni], af1[mi][0],af1[mi][1],af1[mi][2],af1[mi][3],
                 bf1[ni][0],bf1[ni][1]);
    stage = (stage+1==S)? 0 : stage+1;
  }
  #pragma unroll
  for (int mi=0;mi<MI;mi++){
    int r=row0+wm+mi*16+g;
    #pragma unroll
    for (int ni=0;ni<NI;ni++){
      int c=col0+wn+ni*8+2*tig;
      if (c+1<Nn){
        #pragma unroll
        for (int half=0;half<2;half++){
          int rr=r+half*8;
          float v0=acc[mi][ni][half*2+0], v1=acc[mi][ni][half*2+1];
          if (emul){ v0*=emul[(size_t)rr*Nn+c]; v1*=emul[(size_t)rr*Nn+c+1]; }
          if (bias){ v0+=bias[c]; v1+=bias[c+1]; }
          if (act==1){
            v0=0.5f*v0*(1.f+erff(v0*0.70710678118654752f));
            v1=0.5f*v1*(1.f+erff(v1*0.70710678118654752f));
          }
          *(float2*)&Cmat[(size_t)rr*Nn+c]=make_float2(v0,v1);
        }
      }
    }
  }
}

// ---------------- mixbar: warp per query ----------------
__global__ void mixbar2_kernel(const float* __restrict__ wk, const float* __restrict__ wb,
                               const float* __restrict__ feats){
  int warp=threadIdx.x>>5, lane=threadIdx.x&31;
  int q=blockIdx.x*8+warp;
  const float4* q4=(const float4*)g_q;
  float4 qa=q4[q*64+lane], qb=q4[q*64+32+lane];
  const float4* w4=(const float4*)wk;
  float logit[8];
  #pragma unroll
  for (int k=0;k<8;k++){
    float4 wa=w4[k*64+lane], wb4=w4[k*64+32+lane];
    float p=qa.x*wa.x+qa.y*wa.y+qa.z*wa.z+qa.w*wa.w
           +qb.x*wb4.x+qb.y*wb4.y+qb.z*wb4.z+qb.w*wb4.w;
    logit[k]=warpSum(p)+wb[k];
  }
  float m=logit[0];
  #pragma unroll
  for (int k=1;k<8;k++) m=fmaxf(m,logit[k]);
  float s=0.f; float kw[8];
  #pragma unroll
  for (int k=0;k<8;k++){ kw[k]=expf(logit[k]-m); s+=kw[k]; }
  float inv=1.f/s;
  const float4* f4=(const float4*)feats;
  float4 acc0=make_float4(0,0,0,0), acc1=make_float4(0,0,0,0);
  #pragma unroll
  for (int k=0;k<8;k++){
    float w=kw[k]*inv;
    int idx=g_idx[q*8+k];
    float4 fa=f4[(size_t)idx*64+lane], fb=f4[(size_t)idx*64+32+lane];
    acc0.x+=w*fa.x; acc0.y+=w*fa.y; acc0.z+=w*fa.z; acc0.w+=w*fa.w;
    acc1.x+=w*fb.x; acc1.y+=w*fb.y; acc1.z+=w*fb.z; acc1.w+=w*fb.w;
  }
  float4* o4=(float4*)g_fbar;
  o4[q*64+lane]=acc0; o4[q*64+32+lane]=acc1;
}

// ---------------- warp-per-row LayerNorm: out = LN(a + b) ----------------
__global__ void lnw_kernel(float* __restrict__ out, const float* __restrict__ a,
                           const float* __restrict__ b){
  int row=blockIdx.x*8 + (threadIdx.x>>5), lane=threadIdx.x&31;
  const float4* a4=(const float4*)a; const float4* b4=(const float4*)b;
  float4 v0=a4[row*64+lane], v1=a4[row*64+32+lane];
  float4 w0=b4[row*64+lane], w1=b4[row*64+32+lane];
  v0.x+=w0.x;v0.y+=w0.y;v0.z+=w0.z;v0.w+=w0.w;
  v1.x+=w1.x;v1.y+=w1.y;v1.z+=w1.z;v1.w+=w1.w;
  float s=warpSum(v0.x+v0.y+v0.z+v0.w+v1.x+v1.y+v1.z+v1.w);
  float mean=s*(1.f/DM);
  float d0x=v0.x-mean,d0y=v0.y-mean,d0z=v0.z-mean,d0w=v0.w-mean;
  float d1x=v1.x-mean,d1y=v1.y-mean,d1z=v1.z-mean,d1w=v1.w-mean;
  float vs=warpSum(d0x*d0x+d0y*d0y+d0z*d0z+d0w*d0w+d1x*d1x+d1y*d1y+d1z*d1z+d1w*d1w);
  float r=rsqrtf(vs*(1.f/DM)+1e-5f);
  float4* o4=(float4*)out;
  o4[row*64+lane]   =make_float4(d0x*r,d0y*r,d0z*r,d0w*r);
  o4[row*64+32+lane]=make_float4(d1x*r,d1y*r,d1z*r,d1w*r);
}

// ---------------- conv + silu: thread = (b, c4, 8 timesteps) ----------------
__global__ void conv8_kernel(const float* __restrict__ wconv, const float* __restrict__ bconv){
  int id=blockIdx.x*blockDim.x+threadIdx.x;
  int c4=id%160; int t8=(id/160)%(QN/8); int b=id/(160*(QN/8));
  int t0=t8*8;
  const float4* bc4=(const float4*)bconv;
  float4 bias=bc4[c4];
  const float4* w4=(const float4*)wconv;
  float4 w0=w4[c4*4+0], w1=w4[c4*4+1], w2=w4[c4*4+2], w3=w4[c4*4+3];
  const float4* p4=(const float4*)g_proj;
  float4 xv[11];
  #pragma unroll
  for (int i=0;i<11;i++){
    int tt=t0-3+i;
    xv[i] = (tt>=0)? p4[(size_t)(b*QN+tt)*(NPROJN/4) + DINN/4 + c4]
                   : make_float4(0.f,0.f,0.f,0.f);
  }
  float4* ob=(float4*)g_xbc;
  #pragma unroll
  for (int u=0;u<8;u++){
    float4 acc=bias;
    #pragma unroll
    for (int j=0;j<4;j++){
      float4 x=xv[u+j];
      acc.x+=x.x*(&w0.x)[j]; acc.y+=x.y*(&w1.x)[j];
      acc.z+=x.z*(&w2.x)[j]; acc.w+=x.w*(&w3.x)[j];
    }
    acc.x*=sigmoidf_(acc.x); acc.y*=sigmoidf_(acc.y);
    acc.z*=sigmoidf_(acc.z); acc.w*=sigmoidf_(acc.w);
    ob[(size_t)(b*QN+t0+u)*160 + c4]=acc;
  }
}

// ---------------- chunkH: MMA version (Hc = X^T · Bw), pad-76 k-major smem ----------------
__global__ void __launch_bounds__(256) chunkH_kernel(const float* __restrict__ alog,
                                                     const float* __restrict__ dtb){
  __shared__ float Xt[HDIM][PAD];
  __shared__ float Bwt[STATE][PAD];
  __shared__ float La[CSZ], wv[CSZ];
  int bid=blockIdx.x;
  int c=bid%NCH, h=(bid/NCH)%NH, b=bid/(NCH*NH);
  int tid=threadIdx.x;
  int r0=b*QN + c*CSZ;
  float dtloc=0.f;
  if (tid<CSZ){
    int row=r0+tid;
    float raw = g_proj[(size_t)row*NPROJN + DINN+CONVN + h] + dtb[h];
    dtloc = raw>20.f? raw : log1pf(expf(raw));
    g_dts[row*NH+h]=dtloc;
    float A=-expf(alog[h]);
    La[tid]=dtloc*A;
  }
  __syncthreads();
  for (int o=1;o<CSZ;o<<=1){
    float v=0.f;
    if (tid<CSZ && tid>=o) v=La[tid-o];
    __syncthreads();
    if (tid<CSZ) La[tid]+=v;
    __syncthreads();
  }
  if (tid<CSZ) g_Las[(r0+tid)*NH+h]=La[tid];
  __syncthreads();
  if (tid<CSZ) wv[tid]=expf(La[CSZ-1]-La[tid])*dtloc;
  __syncthreads();
  for (int i=tid;i<CSZ*STATE;i+=256){
    int s=i>>6, k=i&63;
    const float* xr=&g_xbc[(size_t)(r0+s)*CONVN];
    Xt[k][s]=xr[h*HDIM+k];
    Bwt[k][s]=xr[DINN+k]*wv[s];
  }
  __syncthreads();
  int warp=tid>>5, lane=tid&31, g=lane>>2, tig=lane&3;
  int wm=(warp&3)*16;
  int wn0=(warp>>2)*16;
  float acc[2][2][4];
  #pragma unroll
  for (int r=0;r<2;r++)
    #pragma unroll
    for (int q8=0;q8<2;q8++)
      #pragma unroll
      for (int e=0;e<4;e++) acc[r][q8][e]=0.f;
  for (int ks=0;ks<CSZ;ks+=8){
    uint32_t a0=fu(Xt[wm+g][ks+tig]),   a1=fu(Xt[wm+8+g][ks+tig]);
    uint32_t a2=fu(Xt[wm+g][ks+tig+4]), a3=fu(Xt[wm+8+g][ks+tig+4]);
    #pragma unroll
    for (int r=0;r<2;r++){
      int nb=wn0+r*32;
      #pragma unroll
      for (int q8=0;q8<2;q8++){
        uint32_t b0=fu(Bwt[nb+q8*8+g][ks+tig]);
        uint32_t b1=fu(Bwt[nb+q8*8+g][ks+tig+4]);
        mma_tf32(acc[r][q8], a0,a1,a2,a3, b0,b1);
      }
    }
  }
  float* Hg=&g_Hc[(size_t)bid*HDIM*STATE];
  int m0=wm+g, m1=wm+8+g;
  #pragma unroll
  for (int r=0;r<2;r++){
    #pragma unroll
    for (int q8=0;q8<2;q8++){
      int cc=wn0+r*32+q8*8+2*tig;
      Hg[m0*STATE+cc  ]=acc[r][q8][0];
      Hg[m0*STATE+cc+1]=acc[r][q8][1];
      Hg[m1*STATE+cc  ]=acc[r][q8][2];
      Hg[m1*STATE+cc+1]=acc[r][q8][3];
    }
  }
}

// ---------------- carry: 128 blocks ----------------
__global__ void carry_kernel(){
  int bh=blockIdx.x>>3;
  int off=(blockIdx.x&7)*512 + threadIdx.x;
  int b=bh>>3, h=bh&7;
  size_t base0=(size_t)(bh*NCH)*HDIM*STATE;
  float hr=0.f;
  float nxt=g_Hc[base0+off];
  for (int c=0;c<NCH;c++){
    float Lend=g_Las[(b*QN + c*CSZ + CSZ-1)*NH + h];
    float f=expf(Lend);
    float cur=nxt;
    if (c+1<NCH) nxt=g_Hc[base0+(size_t)(c+1)*HDIM*STATE+off];
    g_Hin[base0+(size_t)c*HDIM*STATE+off]=hr;
    hr=f*hr+cur;
  }
}

// ---------------- pyfull: 3-phase MMA ----------------
#define PY_SMEM (3*64*PAD*4)
__global__ void __launch_bounds__(256) pyfull_kernel(const float* __restrict__ Dh){
  extern __shared__ float dyn[];
  float (*SA)[PAD]=(float(*)[PAD])dyn;
  float (*SB)[PAD]=(float(*)[PAD])(dyn+64*PAD);
  float (*SP)[PAD]=(float(*)[PAD])(dyn+2*64*PAD);
  __shared__ float La[CSZ], dtv[CSZ];
  int bid=blockIdx.x;
  int c=bid%NCH, h=(bid/NCH)%NH, b=bid/(NCH*NH);
  int tid=threadIdx.x;
  int r0=b*QN + c*CSZ;
  if (tid<CSZ){ La[tid]=g_Las[(r0+tid)*NH+h]; dtv[tid]=g_dts[(r0+tid)*NH+h]; }
  for (int i=tid;i<CSZ*STATE;i+=256){
    int t=i>>6, k=i&63;
    const float* xr=&g_xbc[(size_t)(r0+t)*CONVN];
    SA[t][k]=xr[DINN+STATE+k];
    SB[t][k]=xr[DINN+k];
  }
  __syncthreads();
  int warp=tid>>5, lane=tid&31, g=lane>>2, tig=lane&3;
  int wm=(warp&3)*16;
  int wn0=(warp>>2)*16;
  int m0=wm+g, m1=wm+8+g;
  float accp[2][2][4];
  #pragma unroll
  for (int r=0;r<2;r++)
    #pragma unroll
    for (int q8=0;q8<2;q8++)
      #pragma unroll
      for (int e=0;e<4;e++) accp[r][q8][e]=0.f;
  for (int ks=0;ks<STATE;ks+=8){
    uint32_t a0=fu(SA[m0][ks+tig]),   a1=fu(SA[m1][ks+tig]);
    uint32_t a2=fu(SA[m0][ks+tig+4]), a3=fu(SA[m1][ks+tig+4]);
    #pragma unroll
    for (int r=0;r<2;r++){
      int nb=wn0+r*32;
      #pragma unroll
      for (int q8=0;q8<2;q8++){
        uint32_t b0=fu(SB[nb+q8*8+g][ks+tig]);
        uint32_t b1=fu(SB[nb+q8*8+g][ks+tig+4]);
        mma_tf32(accp[r][q8], a0,a1,a2,a3, b0,b1);
      }
    }
  }
  float La0=La[m0], La1=La[m1];
  float Pv[2][2][4];
  #pragma unroll
  for (int r=0;r<2;r++){
    #pragma unroll
    for (int q8=0;q8<2;q8++){
      int s0=wn0+r*32+q8*8+2*tig, s1=s0+1;
      Pv[r][q8][0]=(s0<=m0)? expf(La0-La[s0])*dtv[s0]*accp[r][q8][0] : 0.f;
      Pv[r][q8][1]=(s1<=m0)? expf(La0-La[s1])*dtv[s1]*accp[r][q8][1] : 0.f;
      Pv[r][q8][2]=(s0<=m1)? expf(La1-La[s0])*dtv[s0]*accp[r][q8][2] : 0.f;
      Pv[r][q8][3]=(s1<=m1)? expf(La1-La[s1])*dtv[s1]*accp[r][q8][3] : 0.f;
    }
  }
  __syncthreads();
  #pragma unroll
  for (int r=0;r<2;r++){
    #pragma unroll
    for (int q8=0;q8<2;q8++){
      int s0=wn0+r*32+q8*8+2*tig;
      SP[m0][s0  ]=Pv[r][q8][0];
      SP[m0][s0+1]=Pv[r][q8][1];
      SP[m1][s0  ]=Pv[r][q8][2];
      SP[m1][s0+1]=Pv[r][q8][3];
    }
  }
  const float* Hg=&g_Hin[(size_t)bid*HDIM*STATE];
  for (int i=tid;i<HDIM*STATE;i+=256) SB[i>>6][i&63]=Hg[i];
  __syncthreads();
  float y2[2][2][4];
  #pragma unroll
  for (int r=0;r<2;r++)
    #pragma unroll
    for (int q8=0;q8<2;q8++)
      #pragma unroll
      for (int e=0;e<4;e++) y2[r][q8][e]=0.f;
  for (int ks=0;ks<STATE;ks+=8){
    uint32_t a0=fu(SA[m0][ks+tig]),   a1=fu(SA[m1][ks+tig]);
    uint32_t a2=fu(SA[m0][ks+tig+4]), a3=fu(SA[m1][ks+tig+4]);
    #pragma unroll
    for (int r=0;r<2;r++){
      int nb=wn0+r*32;
      #pragma unroll
      for (int q8=0;q8<2;q8++){
        uint32_t b0=fu(SB[nb+q8*8+g][ks+tig]);
        uint32_t b1=fu(SB[nb+q8*8+g][ks+tig+4]);
        mma_tf32(y2[r][q8], a0,a1,a2,a3, b0,b1);
      }
    }
  }
  __syncthreads();
  for (int i=tid;i<CSZ*HDIM;i+=256){
    int s=i>>6, k=i&63;
    SA[k][s]=g_xbc[(size_t)(r0+s)*CONVN + h*HDIM + k];
  }
  __syncthreads();
  float y1[2][2][4];
  #pragma unroll
  for (int r=0;r<2;r++)
    #pragma unroll
    for (int q8=0;q8<2;q8++)
      #pragma unroll
      for (int e=0;e<4;e++) y1[r][q8][e]=0.f;
  for (int ks=0;ks<CSZ;ks+=8){
    uint32_t a0=fu(SP[m0][ks+tig]),   a1=fu(SP[m1][ks+tig]);
    uint32_t a2=fu(SP[m0][ks+tig+4]), a3=fu(SP[m1][ks+tig+4]);
    #pragma unroll
    for (int r=0;r<2;r++){
      int nb=wn0+r*32;
      #pragma unroll
      for (int q8=0;q8<2;q8++){
        uint32_t b0=fu(SA[nb+q8*8+g][ks+tig]);
        uint32_t b1=fu(SA[nb+q8*8+g][ks+tig+4]);
        mma_tf32(y1[r][q8], a0,a1,a2,a3, b0,b1);
      }
    }
  }
  float dh=Dh[h];
  float f0=expf(La0), f1=expf(La1);
  #pragma unroll
  for (int r=0;r<2;r++){
    #pragma unroll
    for (int q8=0;q8<2;q8++){
      int hd0=wn0+r*32+q8*8+2*tig, hd1=hd0+1;
      size_t o0=(size_t)(r0+m0)*DINN + h*HDIM;
      size_t o1=(size_t)(r0+m1)*DINN + h*HDIM;
      g_y[o0+hd0]=y1[r][q8][0] + dh*SA[hd0][m0] + f0*y2[r][q8][0];
      g_y[o0+hd1]=y1[r][q8][1] + dh*SA[hd1][m0] + f0*y2[r][q8][1];
      g_y[o1+hd0]=y1[r][q8][2] + dh*SA[hd0][m1] + f1*y2[r][q8][2];
      g_y[o1+hd1]=y1[r][q8][3] + dh*SA[hd1][m1] + f1*y2[r][q8][3];
    }
  }
}

// ---------------- warp-per-row gated RMSNorm over 512 ----------------
__global__ void gate_rmsw_kernel(const float* __restrict__ rmsw){
  int row=blockIdx.x*8 + (threadIdx.x>>5), lane=threadIdx.x&31;
  const float4* y4=(const float4*)g_y;
  const float4* p4=(const float4*)g_proj;
  const float4* w4=(const float4*)rmsw;
  float4 gg[4];
  float ssum=0.f;
  #pragma unroll
  for (int i=0;i<4;i++){
    float4 y=y4[(size_t)row*128 + i*32 + lane];
    float4 z=p4[(size_t)row*(NPROJN/4) + i*32 + lane];
    gg[i].x=y.x*(z.x*sigmoidf_(z.x));
    gg[i].y=y.y*(z.y*sigmoidf_(z.y));
    gg[i].z=y.z*(z.z*sigmoidf_(z.z));
    gg[i].w=y.w*(z.w*sigmoidf_(z.w));
    ssum+=gg[i].x*gg[i].x+gg[i].y*gg[i].y+gg[i].z*gg[i].z+gg[i].w*gg[i].w;
  }
  ssum=warpSum(ssum);
  float r=rsqrtf(ssum*(1.f/DINN)+1e-5f);
  float4* o4=(float4*)g_gated;
  #pragma unroll
  for (int i=0;i<4;i++){
    float4 w=w4[i*32+lane];
    o4[(size_t)row*128 + i*32 + lane]=make_float4(gg[i].x*r*w.x, gg[i].y*r*w.y,
                                                  gg[i].z*r*w.z, gg[i].w*r*w.w);
  }
}

// ---------------- warp-per-row unsort + average + residual + LN ----------------
__global__ void merge_lnw_kernel(){
  int q=blockIdx.x*8 + (threadIdx.x>>5), lane=threadIdx.x&31;
  int i0=g_inv[q], i1=g_inv[QN+q];
  const float4* x4=(const float4*)g_x;
  const float4* s4=(const float4*)g_ssmout;
  float4 v0=x4[q*64+lane], v1=x4[q*64+32+lane];
  float4 a0=s4[(size_t)i0*64+lane], a1=s4[(size_t)i0*64+32+lane];
  float4 b0=s4[(size_t)(QN+i1)*64+lane], b1=s4[(size_t)(QN+i1)*64+32+lane];
  v0.x+=0.5f*(a0.x+b0.x); v0.y+=0.5f*(a0.y+b0.y);
  v0.z+=0.5f*(a0.z+b0.z); v0.w+=0.5f*(a0.w+b0.w);
  v1.x+=0.5f*(a1.x+b1.x); v1.y+=0.5f*(a1.y+b1.y);
  v1.z+=0.5f*(a1.z+b1.z); v1.w+=0.5f*(a1.w+b1.w);
  float s=warpSum(v0.x+v0.y+v0.z+v0.w+v1.x+v1.y+v1.z+v1.w);
  float mean=s*(1.f/DM);
  float d0x=v0.x-mean,d0y=v0.y-mean,d0z=v0.z-mean,d0w=v0.w-mean;
  float d1x=v1.x-mean,d1y=v1.y-mean,d1z=v1.z-mean,d1w=v1.w-mean;
  float vs=warpSum(d0x*d0x+d0y*d0y+d0z*d0z+d0w*d0w+d1x*d1x+d1y*d1y+d1z*d1z+d1w*d1w);
  float r=rsqrtf(vs*(1.f/DM)+1e-5f);
  float4* o4=(float4*)g_x;
  o4[q*64+lane]   =make_float4(d0x*r,d0y*r,d0z*r,d0w*r);
  o4[q*64+32+lane]=make_float4(d1x*r,d1y*r,d1z*r,d1w*r);
}

// =====================================================================
extern "C" void kernel_launch(void* const* d_in, const int* in_sizes, int n_in,
                              void* d_out, int out_size){
  const float* query      = (const float*)d_in[0];
  const float* query_pos  = (const float*)d_in[1];
  const float* inst_feats = (const float*)d_in[2];
  const float* sp_coords  = (const float*)d_in[3];
  const float* w_q  = (const float*)d_in[4];
  const float* w_v  = (const float*)d_in[5];
  const float* w_o  = (const float*)d_in[6];
  const float* w_k  = (const float*)d_in[7];
  const float* w_b  = (const float*)d_in[8];
  const float* Win  = (const float*)d_in[9];
  const float* Wconv= (const float*)d_in[10];
  const float* bconv= (const float*)d_in[11];
  const float* Alog = (const float*)d_in[12];
  const float* Dh   = (const float*)d_in[13];
  const float* dtb  = (const float*)d_in[14];
  const float* rmsw = (const float*)d_in[15];
  const float* Wout = (const float*)d_in[16];
  const float* fw1  = (const float*)d_in[17];
  const float* fb1  = (const float*)d_in[18];
  const float* fw2  = (const float*)d_in[19];
  const float* fb2  = (const float*)d_in[20];
  const int*   order= (const int*)  d_in[21];
  float* out = (float*)d_out;

  float *pq,*pfbar,*pvbar,*ptmp,*px,*pproj,*pgated,*pssm,*pffnh;
  cudaGetSymbolAddress((void**)&pq,    g_q);
  cudaGetSymbolAddress((void**)&pfbar, g_fbar);
  cudaGetSymbolAddress((void**)&pvbar, g_vbar);
  cudaGetSymbolAddress((void**)&ptmp,  g_tmp);
  cudaGetSymbolAddress((void**)&px,    g_x);
  cudaGetSymbolAddress((void**)&pproj, g_proj);
  cudaGetSymbolAddress((void**)&pgated,g_gated);
  cudaGetSymbolAddress((void**)&pssm,  g_ssmout);
  cudaGetSymbolAddress((void**)&pffnh, g_ffnh);

  static bool attr_done=false;
  if (!attr_done){
    cudaFuncSetAttribute(pyfull_kernel, cudaFuncAttributeMaxDynamicSharedMemorySize, PY_SMEM);
    attr_done=true;
  }

  auto gridS=[](int m,int n){ return dim3((unsigned)(n/32),(unsigned)(m/64)); };
  auto gridB=[](int m,int n){ return dim3((unsigned)((n+63)/64),(unsigned)(m/128)); };

  // --- stage 1 ---
  knn_kernel<<<QN/8,256>>>(query_pos, sp_coords, order);
  tgemm_kernel<64,32,16,16,256,5><<<gridS(QN,DM),256>>>(query, w_q, nullptr, nullptr, nullptr, pq, QN, DM, DM, 0);
  mixbar2_kernel<<<QN/8,256>>>(w_k, w_b, inst_feats);
  tgemm_kernel<64,32,16,16,256,5><<<gridS(QN,DM),256>>>(pfbar, w_v, nullptr, pq, nullptr, pvbar, QN, DM, DM, 0);
  tgemm_kernel<64,32,16,16,256,5><<<gridS(QN,DM),256>>>(pvbar, w_o, nullptr, nullptr, nullptr, ptmp, QN, DM, DM, 0);
  lnw_kernel<<<QN/8,256>>>(px, ptmp, query);

  // --- stage 2: two Mamba2 layers (serialize gather fused into proj GEMM A-load;
  //     second LN dropped — input is already a LayerNorm output, LN is idempotent) ---
  for (int l=0;l<2;l++){
    tgemm_kernel<128,64,32,32,256,3><<<gridB(2*QN,NPROJN),256>>>(px,
        Win + (size_t)l*NPROJN*DM, nullptr, nullptr, order, pproj, 2*QN, NPROJN, DM, 0);
    conv8_kernel<<<(2*(QN/8)*160)/256,256>>>(Wconv + (size_t)l*CONVN*4, bconv + (size_t)l*CONVN);
    chunkH_kernel<<<2*NH*NCH,256>>>(Alog + l*NH, dtb + l*NH);
    carry_kernel<<<2*NH*8,512>>>();
    pyfull_kernel<<<2*NH*NCH,256,PY_SMEM>>>(Dh + l*NH);
    gate_rmsw_kernel<<<2*QN/8,256>>>(rmsw + (size_t)l*DINN);
    tgemm_kernel<64,32,16,16,256,5><<<gridS(2*QN,DM),256>>>(pgated,
        Wout + (size_t)l*DM*DINN, nullptr, nullptr, nullptr, pssm, 2*QN, DM, DINN, 0);
    merge_lnw_kernel<<<QN/8,256>>>();
  }

  // --- stage 3: FFN + final LN ---
  tgemm_kernel<128,64,32,32,256,3><<<gridB(QN,HIDN),256>>>(px, fw1, fb1, nullptr, nullptr, pffnh, QN, HIDN, DM, 1);
  tgemm_kernel<64,32,16,16,256,5><<<gridS(QN,DM),256>>>(pffnh, fw2, fb2, nullptr, nullptr, ptmp, QN, DM, HIDN, 0);
  lnw_kernel<<<QN/8,256>>>(out, ptmp, px);
}

// round 16
// speedup vs baseline: 1.1169x; 1.0079x over previous
#include <cuda_runtime.h>
#include <math.h>
#include <stdint.h>

#define QN 2048
#define NPTS 32768
#define DM 256
#define KNN 8
#define NH 8
#define HDIM 64
#define STATE 64
#define DINN 512
#define CONVN 640
#define NPROJN 1160
#define HIDN 1024
#define CSZ 64
#define NCH 32
#define PAD 76

// ---------------- scratch ----------------
__device__ float g_q[QN*DM];
__device__ float g_fbar[QN*DM];
__device__ float g_vbar[QN*DM];
__device__ float g_x[QN*DM];
__device__ float g_tmp[QN*DM];
__device__ int   g_idx[QN*KNN];
__device__ int   g_inv[2*QN];
__device__ float g_proj[2*QN*NPROJN];
__device__ float g_xbc[2*QN*CONVN];
__device__ float g_dts[2*QN*NH];
__device__ float g_Las[2*QN*NH];
__device__ float g_Hc[2*NH*NCH*HDIM*STATE];
__device__ float g_Hin[2*NH*NCH*HDIM*STATE];
__device__ float g_y[2*QN*DINN];
__device__ float g_gated[2*QN*DINN];
__device__ float g_ssmout[2*QN*DM];
__device__ float g_ffnh[QN*HIDN];

__device__ __forceinline__ float sigmoidf_(float x){ return 1.f/(1.f+expf(-x)); }
__device__ __forceinline__ float warpSum(float v){
  #pragma unroll
  for (int o=16;o;o>>=1) v += __shfl_xor_sync(0xffffffffu, v, o);
  return v;
}
__device__ __forceinline__ uint32_t fu(float x){ return __float_as_uint(x); }
__device__ __forceinline__ void mma_tf32(float* d, uint32_t a0,uint32_t a1,uint32_t a2,uint32_t a3,
                                         uint32_t b0,uint32_t b1){
  asm volatile(
    "mma.sync.aligned.m16n8k8.row.col.f32.tf32.tf32.f32 "
    "{%0,%1,%2,%3}, {%4,%5,%6,%7}, {%8,%9}, {%0,%1,%2,%3};"
    : "+f"(d[0]),"+f"(d[1]),"+f"(d[2]),"+f"(d[3])
    : "r"(a0),"r"(a1),"r"(a2),"r"(a3),"r"(b0),"r"(b1));
}
__device__ __forceinline__ void cpa16(uint32_t s, const float* g, bool v){
  int sz = v?16:0;
  asm volatile("cp.async.cg.shared.global [%0], [%1], 16, %2;" :: "r"(s), "l"(g), "r"(sz));
}

// ---------------- small-GEMM body (64x32, 8 warps, S=5), smem passed in ----------------
// C[M,N] = A * B^T (+emul). Used standalone and inside the union kernel.
__device__ __forceinline__ void small_gemm_body(
    float* smem, int bx, int by,
    const float* __restrict__ A, const float* __restrict__ B,
    const float* __restrict__ bias, const float* __restrict__ emul,
    float* __restrict__ Cmat, int Nn, int Kk, int act){
  constexpr int S=5, ROWS=96, SLOTS=ROWS*4;
  float (*Sm)[ROWS][20]=(float(*)[ROWS][20])smem;
  int tid=threadIdx.x, warp=tid>>5, lane=tid&31;
  int wm=(warp&3)*16, wn=(warp>>2)*16;
  int g=lane>>2, tig=lane&3;
  int row0=by*64, col0=bx*32;

  float acc[2][4];
  #pragma unroll
  for (int ni=0;ni<2;ni++)
    #pragma unroll
    for (int r=0;r<4;r++) acc[ni][r]=0.f;

  const float* gp[2]; uint32_t so[2]; bool actv[2];
  #pragma unroll
  for (int i=0;i<2;i++){
    int idx=tid+i*256;
    actv[i]=(idx<SLOTS);
    int idc=actv[i]? idx:0;
    int r=idc>>2, c=(idc&3)<<2;
    if (r<64) gp[i]=A+(size_t)(row0+r)*Kk+c;
    else      gp[i]=B+(size_t)(col0+(r-64))*Kk+c;
    so[i]=(uint32_t)__cvta_generic_to_shared(&Sm[0][r][c]);
  }
  constexpr uint32_t STGB=ROWS*20*4;
  auto issue=[&](int stage, int k0){
    #pragma unroll
    for (int i=0;i<2;i++)
      if (actv[i]) cpa16(so[i]+stage*STGB, gp[i]+k0, true);
  };

  int KT=Kk>>4;
  #pragma unroll
  for (int s=0;s<S-1;s++){
    if (s<KT) issue(s, s<<4);
    asm volatile("cp.async.commit_group;" ::: "memory");
  }
  int stage=0;
  for (int kt=0;kt<KT;kt++){
    asm volatile("cp.async.wait_group %0;" :: "n"(S-2) : "memory");
    __syncthreads();
    int p=stage;
    uint32_t af0[4], bf0[2][2];
    {
      int m=wm+g;
      af0[0]=fu(Sm[p][m  ][tig  ]); af0[1]=fu(Sm[p][m+8][tig  ]);
      af0[2]=fu(Sm[p][m  ][tig+4]); af0[3]=fu(Sm[p][m+8][tig+4]);
      #pragma unroll
      for (int ni=0;ni<2;ni++){
        int n=64+wn+ni*8+g;
        bf0[ni][0]=fu(Sm[p][n][tig  ]);
        bf0[ni][1]=fu(Sm[p][n][tig+4]);
      }
    }
    int nt=kt+S-1;
    if (nt<KT) issue(nt%S, nt<<4);
    asm volatile("cp.async.commit_group;" ::: "memory");
    uint32_t af1[4], bf1[2][2];
    {
      int m=wm+g;
      af1[0]=fu(Sm[p][m  ][8+tig  ]); af1[1]=fu(Sm[p][m+8][8+tig  ]);
      af1[2]=fu(Sm[p][m  ][8+tig+4]); af1[3]=fu(Sm[p][m+8][8+tig+4]);
      #pragma unroll
      for (int ni=0;ni<2;ni++){
        int n=64+wn+ni*8+g;
        bf1[ni][0]=fu(Sm[p][n][8+tig  ]);
        bf1[ni][1]=fu(Sm[p][n][8+tig+4]);
      }
    }
    #pragma unroll
    for (int ni=0;ni<2;ni++)
      mma_tf32(acc[ni], af0[0],af0[1],af0[2],af0[3], bf0[ni][0],bf0[ni][1]);
    #pragma unroll
    for (int ni=0;ni<2;ni++)
      mma_tf32(acc[ni], af1[0],af1[1],af1[2],af1[3], bf1[ni][0],bf1[ni][1]);
    stage = (stage+1==5)? 0 : stage+1;
  }
  int rr0=row0+wm+g;
  #pragma unroll
  for (int ni=0;ni<2;ni++){
    int c=col0+wn+ni*8+2*tig;
    #pragma unroll
    for (int half=0;half<2;half++){
      int rr=rr0+half*8;
      float v0=acc[ni][half*2+0], v1=acc[ni][half*2+1];
      if (emul){ v0*=emul[(size_t)rr*Nn+c]; v1*=emul[(size_t)rr*Nn+c+1]; }
      if (bias){ v0+=bias[c]; v1+=bias[c+1]; }
      if (act==1){
        v0=0.5f*v0*(1.f+erff(v0*0.70710678118654752f));
        v1=0.5f*v1*(1.f+erff(v1*0.70710678118654752f));
      }
      *(float2*)&Cmat[(size_t)rr*Nn+c]=make_float2(v0,v1);
    }
  }
}

// standalone small GEMM
__global__ void __launch_bounds__(256) sgemm5_kernel(
    const float* __restrict__ A, const float* __restrict__ B,
    const float* __restrict__ bias, const float* __restrict__ emul,
    float* __restrict__ Cmat, int Nn, int Kk, int act){
  __shared__ float smem[5*96*20];
  small_gemm_body(smem, blockIdx.x, blockIdx.y, A, B, bias, emul, Cmat, Nn, Kk, act);
}

// ---------------- UNION: knn (blocks 0..255) ∥ wq GEMM (blocks 256..511) ----------------
#define TPTS 2048
__global__ void __launch_bounds__(256) knn_wq_kernel(
    const float* __restrict__ qpos, const float* __restrict__ spos,
    const int* __restrict__ order,
    const float* __restrict__ query, const float* __restrict__ wq){
  __shared__ float smem_u[5*96*20];   // 38.4KB ≥ knn's 32KB float4[2048]
  if (blockIdx.x >= QN/8){
    int bid=blockIdx.x - QN/8;
    small_gemm_body(smem_u, bid&7, bid>>3, query, wq, nullptr, nullptr, g_q, DM, DM, 0);
    return;
  }
  float4* sp=(float4*)smem_u;
  {
    int id=blockIdx.x*256+threadIdx.x;
    if (id<2*QN) g_inv[(id/QN)*QN + order[id]] = id%QN;
  }
  int warp = threadIdx.x>>5, lane = threadIdx.x&31;
  int q = blockIdx.x*8 + warp;
  float qx=qpos[q*3+0], qy=qpos[q*3+1], qz=qpos[q*3+2];
  float qq = qx*qx+qy*qy+qz*qz;
  float bd[8]; int bi[8];
  #pragma unroll
  for (int j=0;j<8;j++){ bd[j]=3.0e38f; bi[j]=0x7fffffff; }
  for (int tile=0;tile<NPTS/TPTS;tile++){
    __syncthreads();
    for (int i=threadIdx.x;i<TPTS;i+=256){
      const float* p=&spos[(size_t)(tile*TPTS+i)*3];
      float sx=p[0], sy=p[1], sz=p[2];
      float ss=sx*sx+sy*sy+sz*sz;
      sp[i]=make_float4(sx,sy,sz,ss);
    }
    __syncthreads();
    for (int p=lane;p<TPTS;p+=32){
      float4 s4=sp[p];
      float dot = qx*s4.x+qy*s4.y+qz*s4.z;
      float d2 = qq + s4.w - 2.f*dot;
      if (d2 < bd[7]){
        bd[7]=d2; bi[7]=tile*TPTS+p;
        for (int j=7;j>0;j--){
          if (bd[j]<bd[j-1]){ float td=bd[j];bd[j]=bd[j-1];bd[j-1]=td;
                              int ti=bi[j];bi[j]=bi[j-1];bi[j-1]=ti; }
          else break;
        }
      }
    }
  }
  for (int off=16;off;off>>=1){
    float od[8]; int oi[8];
    #pragma unroll
    for (int j=0;j<8;j++){
      od[j]=__shfl_xor_sync(0xffffffffu,bd[j],off);
      oi[j]=__shfl_xor_sync(0xffffffffu,bi[j],off);
    }
    float nd[8]; int ni[8]; int a=0,c=0;
    for (int t=0;t<8;t++){
      bool mine;
      if (a>=8) mine=false;
      else if (c>=8) mine=true;
      else mine = (bd[a]<od[c]) || (bd[a]==od[c] && bi[a]<=oi[c]);
      if (mine){ nd[t]=bd[a];ni[t]=bi[a];a++; } else { nd[t]=od[c];ni[t]=oi[c];c++; }
    }
    for (int j=0;j<8;j++){ bd[j]=nd[j]; bi[j]=ni[j]; }
  }
  if (lane==0){
    #pragma unroll
    for (int j=0;j<8;j++) g_idx[q*8+j]=bi[j];
  }
}

// ---------------- big tf32 GEMM (S-stage, frag double buffer, optional row gather) ----------------
template<int TBM_, int TBN_, int WM, int WN, int NTHR, int S>
__global__ void __launch_bounds__(NTHR) tgemm_kernel(
    const float* __restrict__ A, const float* __restrict__ B,
    const float* __restrict__ bias, const float* __restrict__ emul,
    const int* __restrict__ Arows,
    float* __restrict__ Cmat, int M, int Nn, int Kk, int act){
  constexpr int MW = TBM_/WM;
  constexpr int MI = WM/16, NI = WN/8;
  constexpr int ROWS = TBM_+TBN_;
  constexpr int SLOTS = ROWS*4;
  constexpr int CNT = (SLOTS+NTHR-1)/NTHR;
  __shared__ float Sm[S][ROWS][20];
  int tid=threadIdx.x, warp=tid>>5, lane=tid&31;
  int wm=(warp%MW)*WM, wn=(warp/MW)*WN;
  int g=lane>>2, tig=lane&3;
  int row0=blockIdx.y*TBM_, col0=blockIdx.x*TBN_;

  float acc[MI][NI][4];
  #pragma unroll
  for (int mi=0;mi<MI;mi++)
    #pragma unroll
    for (int ni=0;ni<NI;ni++)
      #pragma unroll
      for (int r=0;r<4;r++) acc[mi][ni][r]=0.f;

  const float* gp[CNT]; uint32_t so[CNT]; bool val[CNT]; bool actv[CNT];
  #pragma unroll
  for (int i=0;i<CNT;i++){
    int idx=tid+i*NTHR;
    actv[i]=(idx<SLOTS);
    int idc = actv[i]? idx : 0;
    int r=idc>>2, c=(idc&3)<<2;
    if (r<TBM_){
      int ar = Arows? Arows[row0+r] : (row0+r);
      gp[i]=A+(size_t)ar*Kk+c; val[i]=true;
    }
    else { int rb=r-TBM_; gp[i]=B+(size_t)(col0+rb)*Kk+c; val[i]=(col0+rb)<Nn; }
    so[i]=(uint32_t)__cvta_generic_to_shared(&Sm[0][r][c]);
  }
  constexpr uint32_t STGB=ROWS*20*4;
  auto issue=[&](int stage, int k0){
    #pragma unroll
    for (int i=0;i<CNT;i++)
      if (actv[i]) cpa16(so[i]+stage*STGB, gp[i]+k0, val[i]);
  };

  int KT=Kk>>4;
  #pragma unroll
  for (int s=0;s<S-1;s++){
    if (s<KT) issue(s, s<<4);
    asm volatile("cp.async.commit_group;" ::: "memory");
  }

  int stage=0;
  for (int kt=0;kt<KT;kt++){
    asm volatile("cp.async.wait_group %0;" :: "n"(S-2) : "memory");
    __syncthreads();
    int p=stage;
    uint32_t af0[MI][4], bf0[NI][2];
    #pragma unroll
    for (int mi=0;mi<MI;mi++){
      int m=wm+mi*16+g;
      af0[mi][0]=fu(Sm[p][m  ][tig  ]);
      af0[mi][1]=fu(Sm[p][m+8][tig  ]);
      af0[mi][2]=fu(Sm[p][m  ][tig+4]);
      af0[mi][3]=fu(Sm[p][m+8][tig+4]);
    }
    #pragma unroll
    for (int ni=0;ni<NI;ni++){
      int n=TBM_+wn+ni*8+g;
      bf0[ni][0]=fu(Sm[p][n][tig  ]);
      bf0[ni][1]=fu(Sm[p][n][tig+4]);
    }
    int nt=kt+S-1;
    if (nt<KT) issue(nt%S, nt<<4);
    asm volatile("cp.async.commit_group;" ::: "memory");
    uint32_t af1[MI][4], bf1[NI][2];
    #pragma unroll
    for (int mi=0;mi<MI;mi++){
      int m=wm+mi*16+g;
      af1[mi][0]=fu(Sm[p][m  ][8+tig  ]);
      af1[mi][1]=fu(Sm[p][m+8][8+tig  ]);
      af1[mi][2]=fu(Sm[p][m  ][8+tig+4]);
      af1[mi][3]=fu(Sm[p][m+8][8+tig+4]);
    }
    #pragma unroll
    for (int ni=0;ni<NI;ni++){
      int n=TBM_+wn+ni*8+g;
      bf1[ni][0]=fu(Sm[p][n][8+tig  ]);
      bf1[ni][1]=fu(Sm[p][n][8+tig+4]);
    }
    #pragma unroll
    for (int mi=0;mi<MI;mi++)
      #pragma unroll
      for (int ni=0;ni<NI;ni++)
        mma_tf32(acc[mi][ni], af0[mi][0],af0[mi][1],af0[mi][2],af0[mi][3],
                 bf0[ni][0],bf0[ni][1]);
    #pragma unroll
    for (int mi=0;mi<MI;mi++)
      #pragma unroll
      for (int ni=0;ni<NI;ni++)
        mma_tf32(acc[mi][ni], af1[mi][0],af1[mi][1],af1[mi][2],af1[mi][3],
                 bf1[ni][0],bf1[ni][1]);
    stage = (stage+1==S)? 0 : stage+1;
  }
  #pragma unroll
  for (int mi=0;mi<MI;mi++){
    int r=row0+wm+mi*16+g;
    #pragma unroll
    for (int ni=0;ni<NI;ni++){
      int c=col0+wn+ni*8+2*tig;
      if (c+1<Nn){
        #pragma unroll
        for (int half=0;half<2;half++){
          int rr=r+half*8;
          float v0=acc[mi][ni][half*2+0], v1=acc[mi][ni][half*2+1];
          if (emul){ v0*=emul[(size_t)rr*Nn+c]; v1*=emul[(size_t)rr*Nn+c+1]; }
          if (bias){ v0+=bias[c]; v1+=bias[c+1]; }
          if (act==1){
            v0=0.5f*v0*(1.f+erff(v0*0.70710678118654752f));
            v1=0.5f*v1*(1.f+erff(v1*0.70710678118654752f));
          }
          *(float2*)&Cmat[(size_t)rr*Nn+c]=make_float2(v0,v1);
        }
      }
    }
  }
}

// ---------------- mixbar: warp per query ----------------
__global__ void mixbar2_kernel(const float* __restrict__ wk, const float* __restrict__ wb,
                               const float* __restrict__ feats){
  int warp=threadIdx.x>>5, lane=threadIdx.x&31;
  int q=blockIdx.x*8+warp;
  const float4* q4=(const float4*)g_q;
  float4 qa=q4[q*64+lane], qb=q4[q*64+32+lane];
  const float4* w4=(const float4*)wk;
  float logit[8];
  #pragma unroll
  for (int k=0;k<8;k++){
    float4 wa=w4[k*64+lane], wb4=w4[k*64+32+lane];
    float p=qa.x*wa.x+qa.y*wa.y+qa.z*wa.z+qa.w*wa.w
           +qb.x*wb4.x+qb.y*wb4.y+qb.z*wb4.z+qb.w*wb4.w;
    logit[k]=warpSum(p)+wb[k];
  }
  float m=logit[0];
  #pragma unroll
  for (int k=1;k<8;k++) m=fmaxf(m,logit[k]);
  float s=0.f; float kw[8];
  #pragma unroll
  for (int k=0;k<8;k++){ kw[k]=expf(logit[k]-m); s+=kw[k]; }
  float inv=1.f/s;
  const float4* f4=(const float4*)feats;
  float4 acc0=make_float4(0,0,0,0), acc1=make_float4(0,0,0,0);
  #pragma unroll
  for (int k=0;k<8;k++){
    float w=kw[k]*inv;
    int idx=g_idx[q*8+k];
    float4 fa=f4[(size_t)idx*64+lane], fb=f4[(size_t)idx*64+32+lane];
    acc0.x+=w*fa.x; acc0.y+=w*fa.y; acc0.z+=w*fa.z; acc0.w+=w*fa.w;
    acc1.x+=w*fb.x; acc1.y+=w*fb.y; acc1.z+=w*fb.z; acc1.w+=w*fb.w;
  }
  float4* o4=(float4*)g_fbar;
  o4[q*64+lane]=acc0; o4[q*64+32+lane]=acc1;
}

// ---------------- warp-per-row LayerNorm: out = LN(a + b) ----------------
__global__ void lnw_kernel(float* __restrict__ out, const float* __restrict__ a,
                           const float* __restrict__ b){
  int row=blockIdx.x*8 + (threadIdx.x>>5), lane=threadIdx.x&31;
  const float4* a4=(const float4*)a; const float4* b4=(const float4*)b;
  float4 v0=a4[row*64+lane], v1=a4[row*64+32+lane];
  float4 w0=b4[row*64+lane], w1=b4[row*64+32+lane];
  v0.x+=w0.x;v0.y+=w0.y;v0.z+=w0.z;v0.w+=w0.w;
  v1.x+=w1.x;v1.y+=w1.y;v1.z+=w1.z;v1.w+=w1.w;
  float s=warpSum(v0.x+v0.y+v0.z+v0.w+v1.x+v1.y+v1.z+v1.w);
  float mean=s*(1.f/DM);
  float d0x=v0.x-mean,d0y=v0.y-mean,d0z=v0.z-mean,d0w=v0.w-mean;
  float d1x=v1.x-mean,d1y=v1.y-mean,d1z=v1.z-mean,d1w=v1.w-mean;
  float vs=warpSum(d0x*d0x+d0y*d0y+d0z*d0z+d0w*d0w+d1x*d1x+d1y*d1y+d1z*d1z+d1w*d1w);
  float r=rsqrtf(vs*(1.f/DM)+1e-5f);
  float4* o4=(float4*)out;
  o4[row*64+lane]   =make_float4(d0x*r,d0y*r,d0z*r,d0w*r);
  o4[row*64+32+lane]=make_float4(d1x*r,d1y*r,d1z*r,d1w*r);
}

// ---------------- conv + silu ----------------
__global__ void conv8_kernel(const float* __restrict__ wconv, const float* __restrict__ bconv){
  int id=blockIdx.x*blockDim.x+threadIdx.x;
  int c4=id%160; int t8=(id/160)%(QN/8); int b=id/(160*(QN/8));
  int t0=t8*8;
  const float4* bc4=(const float4*)bconv;
  float4 bias=bc4[c4];
  const float4* w4=(const float4*)wconv;
  float4 w0=w4[c4*4+0], w1=w4[c4*4+1], w2=w4[c4*4+2], w3=w4[c4*4+3];
  const float4* p4=(const float4*)g_proj;
  float4 xv[11];
  #pragma unroll
  for (int i=0;i<11;i++){
    int tt=t0-3+i;
    xv[i] = (tt>=0)? p4[(size_t)(b*QN+tt)*(NPROJN/4) + DINN/4 + c4]
                   : make_float4(0.f,0.f,0.f,0.f);
  }
  float4* ob=(float4*)g_xbc;
  #pragma unroll
  for (int u=0;u<8;u++){
    float4 acc=bias;
    #pragma unroll
    for (int j=0;j<4;j++){
      float4 x=xv[u+j];
      acc.x+=x.x*(&w0.x)[j]; acc.y+=x.y*(&w1.x)[j];
      acc.z+=x.z*(&w2.x)[j]; acc.w+=x.w*(&w3.x)[j];
    }
    acc.x*=sigmoidf_(acc.x); acc.y*=sigmoidf_(acc.y);
    acc.z*=sigmoidf_(acc.z); acc.w*=sigmoidf_(acc.w);
    ob[(size_t)(b*QN+t0+u)*160 + c4]=acc;
  }
}

// ---------------- chunkH: MMA, pad-76 ----------------
__global__ void __launch_bounds__(256) chunkH_kernel(const float* __restrict__ alog,
                                                     const float* __restrict__ dtb){
  __shared__ float Xt[HDIM][PAD];
  __shared__ float Bwt[STATE][PAD];
  __shared__ float La[CSZ], wv[CSZ];
  int bid=blockIdx.x;
  int c=bid%NCH, h=(bid/NCH)%NH, b=bid/(NCH*NH);
  int tid=threadIdx.x;
  int r0=b*QN + c*CSZ;
  float dtloc=0.f;
  if (tid<CSZ){
    int row=r0+tid;
    float raw = g_proj[(size_t)row*NPROJN + DINN+CONVN + h] + dtb[h];
    dtloc = raw>20.f? raw : log1pf(expf(raw));
    g_dts[row*NH+h]=dtloc;
    float A=-expf(alog[h]);
    La[tid]=dtloc*A;
  }
  __syncthreads();
  for (int o=1;o<CSZ;o<<=1){
    float v=0.f;
    if (tid<CSZ && tid>=o) v=La[tid-o];
    __syncthreads();
    if (tid<CSZ) La[tid]+=v;
    __syncthreads();
  }
  if (tid<CSZ) g_Las[(r0+tid)*NH+h]=La[tid];
  __syncthreads();
  if (tid<CSZ) wv[tid]=expf(La[CSZ-1]-La[tid])*dtloc;
  __syncthreads();
  for (int i=tid;i<CSZ*STATE;i+=256){
    int s=i>>6, k=i&63;
    const float* xr=&g_xbc[(size_t)(r0+s)*CONVN];
    Xt[k][s]=xr[h*HDIM+k];
    Bwt[k][s]=xr[DINN+k]*wv[s];
  }
  __syncthreads();
  int warp=tid>>5, lane=tid&31, g=lane>>2, tig=lane&3;
  int wm=(warp&3)*16;
  int wn0=(warp>>2)*16;
  float acc[2][2][4];
  #pragma unroll
  for (int r=0;r<2;r++)
    #pragma unroll
    for (int q8=0;q8<2;q8++)
      #pragma unroll
      for (int e=0;e<4;e++) acc[r][q8][e]=0.f;
  for (int ks=0;ks<CSZ;ks+=8){
    uint32_t a0=fu(Xt[wm+g][ks+tig]),   a1=fu(Xt[wm+8+g][ks+tig]);
    uint32_t a2=fu(Xt[wm+g][ks+tig+4]), a3=fu(Xt[wm+8+g][ks+tig+4]);
    #pragma unroll
    for (int r=0;r<2;r++){
      int nb=wn0+r*32;
      #pragma unroll
      for (int q8=0;q8<2;q8++){
        uint32_t b0=fu(Bwt[nb+q8*8+g][ks+tig]);
        uint32_t b1=fu(Bwt[nb+q8*8+g][ks+tig+4]);
        mma_tf32(acc[r][q8], a0,a1,a2,a3, b0,b1);
      }
    }
  }
  float* Hg=&g_Hc[(size_t)bid*HDIM*STATE];
  int m0=wm+g, m1=wm+8+g;
  #pragma unroll
  for (int r=0;r<2;r++){
    #pragma unroll
    for (int q8=0;q8<2;q8++){
      int cc=wn0+r*32+q8*8+2*tig;
      Hg[m0*STATE+cc  ]=acc[r][q8][0];
      Hg[m0*STATE+cc+1]=acc[r][q8][1];
      Hg[m1*STATE+cc  ]=acc[r][q8][2];
      Hg[m1*STATE+cc+1]=acc[r][q8][3];
    }
  }
}

// ---------------- carry ----------------
__global__ void carry_kernel(){
  int bh=blockIdx.x>>3;
  int off=(blockIdx.x&7)*512 + threadIdx.x;
  int b=bh>>3, h=bh&7;
  size_t base0=(size_t)(bh*NCH)*HDIM*STATE;
  float hr=0.f;
  float nxt=g_Hc[base0+off];
  for (int c=0;c<NCH;c++){
    float Lend=g_Las[(b*QN + c*CSZ + CSZ-1)*NH + h];
    float f=expf(Lend);
    float cur=nxt;
    if (c+1<NCH) nxt=g_Hc[base0+(size_t)(c+1)*HDIM*STATE+off];
    g_Hin[base0+(size_t)c*HDIM*STATE+off]=hr;
    hr=f*hr+cur;
  }
}

// ---------------- pyfull: 3-phase MMA ----------------
#define PY_SMEM (3*64*PAD*4)
__global__ void __launch_bounds__(256) pyfull_kernel(const float* __restrict__ Dh){
  extern __shared__ float dyn[];
  float (*SA)[PAD]=(float(*)[PAD])dyn;
  float (*SB)[PAD]=(float(*)[PAD])(dyn+64*PAD);
  float (*SP)[PAD]=(float(*)[PAD])(dyn+2*64*PAD);
  __shared__ float La[CSZ], dtv[CSZ];
  int bid=blockIdx.x;
  int c=bid%NCH, h=(bid/NCH)%NH, b=bid/(NCH*NH);
  int tid=threadIdx.x;
  int r0=b*QN + c*CSZ;
  if (tid<CSZ){ La[tid]=g_Las[(r0+tid)*NH+h]; dtv[tid]=g_dts[(r0+tid)*NH+h]; }
  for (int i=tid;i<CSZ*STATE;i+=256){
    int t=i>>6, k=i&63;
    const float* xr=&g_xbc[(size_t)(r0+t)*CONVN];
    SA[t][k]=xr[DINN+STATE+k];
    SB[t][k]=xr[DINN+k];
  }
  __syncthreads();
  int warp=tid>>5, lane=tid&31, g=lane>>2, tig=lane&3;
  int wm=(warp&3)*16;
  int wn0=(warp>>2)*16;
  int m0=wm+g, m1=wm+8+g;
  float accp[2][2][4];
  #pragma unroll
  for (int r=0;r<2;r++)
    #pragma unroll
    for (int q8=0;q8<2;q8++)
      #pragma unroll
      for (int e=0;e<4;e++) accp[r][q8][e]=0.f;
  for (int ks=0;ks<STATE;ks+=8){
    uint32_t a0=fu(SA[m0][ks+tig]),   a1=fu(SA[m1][ks+tig]);
    uint32_t a2=fu(SA[m0][ks+tig+4]), a3=fu(SA[m1][ks+tig+4]);
    #pragma unroll
    for (int r=0;r<2;r++){
      int nb=wn0+r*32;
      #pragma unroll
      for (int q8=0;q8<2;q8++){
        uint32_t b0=fu(SB[nb+q8*8+g][ks+tig]);
        uint32_t b1=fu(SB[nb+q8*8+g][ks+tig+4]);
        mma_tf32(accp[r][q8], a0,a1,a2,a3, b0,b1);
      }
    }
  }
  float La0=La[m0], La1=La[m1];
  float Pv[2][2][4];
  #pragma unroll
  for (int r=0;r<2;r++){
    #pragma unroll
    for (int q8=0;q8<2;q8++){
      int s0=wn0+r*32+q8*8+2*tig, s1=s0+1;
      Pv[r][q8][0]=(s0<=m0)? expf(La0-La[s0])*dtv[s0]*accp[r][q8][0] : 0.f;
      Pv[r][q8][1]=(s1<=m0)? expf(La0-La[s1])*dtv[s1]*accp[r][q8][1] : 0.f;
      Pv[r][q8][2]=(s0<=m1)? expf(La1-La[s0])*dtv[s0]*accp[r][q8][2] : 0.f;
      Pv[r][q8][3]=(s1<=m1)? expf(La1-La[s1])*dtv[s1]*accp[r][q8][3] : 0.f;
    }
  }
  __syncthreads();
  #pragma unroll
  for (int r=0;r<2;r++){
    #pragma unroll
    for (int q8=0;q8<2;q8++){
      int s0=wn0+r*32+q8*8+2*tig;
      SP[m0][s0  ]=Pv[r][q8][0];
      SP[m0][s0+1]=Pv[r][q8][1];
      SP[m1][s0  ]=Pv[r][q8][2];
      SP[m1][s0+1]=Pv[r][q8][3];
    }
  }
  const float* Hg=&g_Hin[(size_t)bid*HDIM*STATE];
  for (int i=tid;i<HDIM*STATE;i+=256) SB[i>>6][i&63]=Hg[i];
  __syncthreads();
  float y2[2][2][4];
  #pragma unroll
  for (int r=0;r<2;r++)
    #pragma unroll
    for (int q8=0;q8<2;q8++)
      #pragma unroll
      for (int e=0;e<4;e++) y2[r][q8][e]=0.f;
  for (int ks=0;ks<STATE;ks+=8){
    uint32_t a0=fu(SA[m0][ks+tig]),   a1=fu(SA[m1][ks+tig]);
    uint32_t a2=fu(SA[m0][ks+tig+4]), a3=fu(SA[m1][ks+tig+4]);
    #pragma unroll
    for (int r=0;r<2;r++){
      int nb=wn0+r*32;
      #pragma unroll
      for (int q8=0;q8<2;q8++){
        uint32_t b0=fu(SB[nb+q8*8+g][ks+tig]);
        uint32_t b1=fu(SB[nb+q8*8+g][ks+tig+4]);
        mma_tf32(y2[r][q8], a0,a1,a2,a3, b0,b1);
      }
    }
  }
  __syncthreads();
  for (int i=tid;i<CSZ*HDIM;i+=256){
    int s=i>>6, k=i&63;
    SA[k][s]=g_xbc[(size_t)(r0+s)*CONVN + h*HDIM + k];
  }
  __syncthreads();
  float y1[2][2][4];
  #pragma unroll
  for (int r=0;r<2;r++)
    #pragma unroll
    for (int q8=0;q8<2;q8++)
      #pragma unroll
      for (int e=0;e<4;e++) y1[r][q8][e]=0.f;
  for (int ks=0;ks<CSZ;ks+=8){
    uint32_t a0=fu(SP[m0][ks+tig]),   a1=fu(SP[m1][ks+tig]);
    uint32_t a2=fu(SP[m0][ks+tig+4]), a3=fu(SP[m1][ks+tig+4]);
    #pragma unroll
    for (int r=0;r<2;r++){
      int nb=wn0+r*32;
      #pragma unroll
      for (int q8=0;q8<2;q8++){
        uint32_t b0=fu(SA[nb+q8*8+g][ks+tig]);
        uint32_t b1=fu(SA[nb+q8*8+g][ks+tig+4]);
        mma_tf32(y1[r][q8], a0,a1,a2,a3, b0,b1);
      }
    }
  }
  float dh=Dh[h];
  float f0=expf(La0), f1=expf(La1);
  #pragma unroll
  for (int r=0;r<2;r++){
    #pragma unroll
    for (int q8=0;q8<2;q8++){
      int hd0=wn0+r*32+q8*8+2*tig, hd1=hd0+1;
      size_t o0=(size_t)(r0+m0)*DINN + h*HDIM;
      size_t o1=(size_t)(r0+m1)*DINN + h*HDIM;
      g_y[o0+hd0]=y1[r][q8][0] + dh*SA[hd0][m0] + f0*y2[r][q8][0];
      g_y[o0+hd1]=y1[r][q8][1] + dh*SA[hd1][m0] + f0*y2[r][q8][1];
      g_y[o1+hd0]=y1[r][q8][2] + dh*SA[hd0][m1] + f1*y2[r][q8][2];
      g_y[o1+hd1]=y1[r][q8][3] + dh*SA[hd1][m1] + f1*y2[r][q8][3];
    }
  }
}

// ---------------- warp-per-row gated RMSNorm over 512 ----------------
__global__ void gate_rmsw_kernel(const float* __restrict__ rmsw){
  int row=blockIdx.x*8 + (threadIdx.x>>5), lane=threadIdx.x&31;
  const float4* y4=(const float4*)g_y;
  const float4* p4=(const float4*)g_proj;
  const float4* w4=(const float4*)rmsw;
  float4 gg[4];
  float ssum=0.f;
  #pragma unroll
  for (int i=0;i<4;i++){
    float4 y=y4[(size_t)row*128 + i*32 + lane];
    float4 z=p4[(size_t)row*(NPROJN/4) + i*32 + lane];
    gg[i].x=y.x*(z.x*sigmoidf_(z.x));
    gg[i].y=y.y*(z.y*sigmoidf_(z.y));
    gg[i].z=y.z*(z.z*sigmoidf_(z.z));
    gg[i].w=y.w*(z.w*sigmoidf_(z.w));
    ssum+=gg[i].x*gg[i].x+gg[i].y*gg[i].y+gg[i].z*gg[i].z+gg[i].w*gg[i].w;
  }
  ssum=warpSum(ssum);
  float r=rsqrtf(ssum*(1.f/DINN)+1e-5f);
  float4* o4=(float4*)g_gated;
  #pragma unroll
  for (int i=0;i<4;i++){
    float4 w=w4[i*32+lane];
    o4[(size_t)row*128 + i*32 + lane]=make_float4(gg[i].x*r*w.x, gg[i].y*r*w.y,
                                                  gg[i].z*r*w.z, gg[i].w*r*w.w);
  }
}

// ---------------- warp-per-row unsort + average + residual + LN ----------------
__global__ void merge_lnw_kernel(){
  int q=blockIdx.x*8 + (threadIdx.x>>5), lane=threadIdx.x&31;
  int i0=g_inv[q], i1=g_inv[QN+q];
  const float4* x4=(const float4*)g_x;
  const float4* s4=(const float4*)g_ssmout;
  float4 v0=x4[q*64+lane], v1=x4[q*64+32+lane];
  float4 a0=s4[(size_t)i0*64+lane], a1=s4[(size_t)i0*64+32+lane];
  float4 b0=s4[(size_t)(QN+i1)*64+lane], b1=s4[(size_t)(QN+i1)*64+32+lane];
  v0.x+=0.5f*(a0.x+b0.x); v0.y+=0.5f*(a0.y+b0.y);
  v0.z+=0.5f*(a0.z+b0.z); v0.w+=0.5f*(a0.w+b0.w);
  v1.x+=0.5f*(a1.x+b1.x); v1.y+=0.5f*(a1.y+b1.y);
  v1.z+=0.5f*(a1.z+b1.z); v1.w+=0.5f*(a1.w+b1.w);
  float s=warpSum(v0.x+v0.y+v0.z+v0.w+v1.x+v1.y+v1.z+v1.w);
  float mean=s*(1.f/DM);
  float d0x=v0.x-mean,d0y=v0.y-mean,d0z=v0.z-mean,d0w=v0.w-mean;
  float d1x=v1.x-mean,d1y=v1.y-mean,d1z=v1.z-mean,d1w=v1.w-mean;
  float vs=warpSum(d0x*d0x+d0y*d0y+d0z*d0z+d0w*d0w+d1x*d1x+d1y*d1y+d1z*d1z+d1w*d1w);
  float r=rsqrtf(vs*(1.f/DM)+1e-5f);
  float4* o4=(float4*)g_x;
  o4[q*64+lane]   =make_float4(d0x*r,d0y*r,d0z*r,d0w*r);
  o4[q*64+32+lane]=make_float4(d1x*r,d1y*r,d1z*r,d1w*r);
}

// =====================================================================
extern "C" void kernel_launch(void* const* d_in, const int* in_sizes, int n_in,
                              void* d_out, int out_size){
  const float* query      = (const float*)d_in[0];
  const float* query_pos  = (const float*)d_in[1];
  const float* inst_feats = (const float*)d_in[2];
  const float* sp_coords  = (const float*)d_in[3];
  const float* w_q  = (const float*)d_in[4];
  const float* w_v  = (const float*)d_in[5];
  const float* w_o  = (const float*)d_in[6];
  const float* w_k  = (const float*)d_in[7];
  const float* w_b  = (const float*)d_in[8];
  const float* Win  = (const float*)d_in[9];
  const float* Wconv= (const float*)d_in[10];
  const float* bconv= (const float*)d_in[11];
  const float* Alog = (const float*)d_in[12];
  const float* Dh   = (const float*)d_in[13];
  const float* dtb  = (const float*)d_in[14];
  const float* rmsw = (const float*)d_in[15];
  const float* Wout = (const float*)d_in[16];
  const float* fw1  = (const float*)d_in[17];
  const float* fb1  = (const float*)d_in[18];
  const float* fw2  = (const float*)d_in[19];
  const float* fb2  = (const float*)d_in[20];
  const int*   order= (const int*)  d_in[21];
  float* out = (float*)d_out;

  float *pq,*pfbar,*pvbar,*ptmp,*px,*pproj,*pgated,*pssm,*pffnh;
  cudaGetSymbolAddress((void**)&pq,    g_q);
  cudaGetSymbolAddress((void**)&pfbar, g_fbar);
  cudaGetSymbolAddress((void**)&pvbar, g_vbar);
  cudaGetSymbolAddress((void**)&ptmp,  g_tmp);
  cudaGetSymbolAddress((void**)&px,    g_x);
  cudaGetSymbolAddress((void**)&pproj, g_proj);
  cudaGetSymbolAddress((void**)&pgated,g_gated);
  cudaGetSymbolAddress((void**)&pssm,  g_ssmout);
  cudaGetSymbolAddress((void**)&pffnh, g_ffnh);

  static bool attr_done=false;
  if (!attr_done){
    cudaFuncSetAttribute(pyfull_kernel, cudaFuncAttributeMaxDynamicSharedMemorySize, PY_SMEM);
    attr_done=true;
  }

  auto gridS=[](int m,int n){ return dim3((unsigned)(n/32),(unsigned)(m/64)); };
  auto gridB=[](int m,int n){ return dim3((unsigned)((n+63)/64),(unsigned)(m/128)); };

  // --- stage 1: knn ∥ wq union, then mixing chain ---
  knn_wq_kernel<<<QN/8 + (QN/64)*(DM/32),256>>>(query_pos, sp_coords, order, query, w_q);
  mixbar2_kernel<<<QN/8,256>>>(w_k, w_b, inst_feats);
  sgemm5_kernel<<<gridS(QN,DM),256>>>(pfbar, w_v, nullptr, pq, pvbar, DM, DM, 0);
  sgemm5_kernel<<<gridS(QN,DM),256>>>(pvbar, w_o, nullptr, nullptr, ptmp, DM, DM, 0);
  lnw_kernel<<<QN/8,256>>>(px, ptmp, query);

  // --- stage 2: two Mamba2 layers ---
  for (int l=0;l<2;l++){
    tgemm_kernel<128,64,32,32,256,3><<<gridB(2*QN,NPROJN),256>>>(px,
        Win + (size_t)l*NPROJN*DM, nullptr, nullptr, order, pproj, 2*QN, NPROJN, DM, 0);
    conv8_kernel<<<(2*(QN/8)*160)/256,256>>>(Wconv + (size_t)l*CONVN*4, bconv + (size_t)l*CONVN);
    chunkH_kernel<<<2*NH*NCH,256>>>(Alog + l*NH, dtb + l*NH);
    carry_kernel<<<2*NH*8,512>>>();
    pyfull_kernel<<<2*NH*NCH,256,PY_SMEM>>>(Dh + l*NH);
    gate_rmsw_kernel<<<2*QN/8,256>>>(rmsw + (size_t)l*DINN);
    sgemm5_kernel<<<gridS(2*QN,DM),256>>>(pgated,
        Wout + (size_t)l*DM*DINN, nullptr, nullptr, pssm, DM, DINN, 0);
    merge_lnw_kernel<<<QN/8,256>>>();
  }

  // --- stage 3: FFN + final LN ---
  tgemm_kernel<128,64,32,32,256,3><<<gridB(QN,HIDN),256>>>(px, fw1, fb1, nullptr, nullptr, pffnh, QN, HIDN, DM, 1);
  sgemm5_kernel<<<gridS(QN,DM),256>>>(pffnh, fw2, fb2, nullptr, ptmp, DM, HIDN, 0);
  lnw_kernel<<<QN/8,256>>>(out, ptmp, px);
}